// round 12
// baseline (speedup 1.0000x reference)
#include <cuda_runtime.h>
#include <cuda_bf16.h>
#include <math.h>
#include <stdint.h>

#define Mm 4
#define Pp 4
#define Ll 2
#define Ss 256
#define Bb 32
#define Ii 256
#define Hh 512
#define Oo 256
#define Gg (3*Hh)
#define Rr (Pp*Bb)

#define WSTRIDE 528
#define SCAN_SMEM_BYTES (48*WSTRIDE*4)

__device__ float g_gi0[(size_t)Mm*Ss*Bb*Gg];
__device__ float g_y0m[(size_t)Mm*Pp*Ss*Bb*Hh];
__device__ float g_gi1[(size_t)Mm*Pp*Ss*Bb*Gg];
__device__ float g_a1 [(size_t)Mm*Pp*Ss*Bb*Hh];
__device__ float g_h0a[Mm*Rr*Hh];
__device__ float g_h0b[Mm*Rr*Hh];
__device__ float g_h1a[Mm*Rr*Hh];
__device__ float g_h1b[Mm*Rr*Hh];
__device__ uint4 g_hp0a[Mm*Rr*128];
__device__ uint4 g_hp0b[Mm*Rr*128];
__device__ uint4 g_hp1a[Mm*Rr*128];
__device__ uint4 g_hp1b[Mm*Rr*128];
__device__ uint4 g_whhp[2 * Mm * Gg * 128];
__device__ unsigned g_sync[8];

__device__ __forceinline__ float tf32r(float x) {
    uint32_t u;
    asm("cvt.rna.tf32.f32 %0, %1;" : "=r"(u) : "f"(x));
    return __uint_as_float(u);
}

__device__ __forceinline__ void mma_tf32(float c[4], const uint32_t a[4], const uint32_t b[2]) {
    asm volatile(
        "mma.sync.aligned.m16n8k8.row.col.f32.tf32.tf32.f32 "
        "{%0,%1,%2,%3},{%4,%5,%6,%7},{%8,%9},{%0,%1,%2,%3};"
        : "+f"(c[0]), "+f"(c[1]), "+f"(c[2]), "+f"(c[3])
        : "r"(a[0]), "r"(a[1]), "r"(a[2]), "r"(a[3]), "r"(b[0]), "r"(b[1]));
}

__device__ __forceinline__ void mma_bf16(float c[4], const uint32_t a[4], const uint32_t b[2]) {
    asm volatile(
        "mma.sync.aligned.m16n8k16.row.col.f32.bf16.bf16.f32 "
        "{%0,%1,%2,%3},{%4,%5,%6,%7},{%8,%9},{%0,%1,%2,%3};"
        : "+f"(c[0]), "+f"(c[1]), "+f"(c[2]), "+f"(c[3])
        : "r"(a[0]), "r"(a[1]), "r"(a[2]), "r"(a[3]), "r"(b[0]), "r"(b[1]));
}

// MUFU-based activations (saturation-safe at +/-inf)
__device__ __forceinline__ float fast_sigmoid(float x) {
    return 1.0f / (1.0f + __expf(-x));
}
__device__ __forceinline__ float fast_tanh(float x) {
    return 1.0f - 2.0f / (__expf(2.0f * x) + 1.0f);
}

__device__ __forceinline__ uint2 pack_hilo(float x0, float x1) {
    __nv_bfloat162 hi = __floats2bfloat162_rn(x0, x1);
    float l0 = x0 - __bfloat162float(hi.x);
    float l1 = x1 - __bfloat162float(hi.y);
    __nv_bfloat162 lo = __floats2bfloat162_rn(l0, l1);
    uint2 r;
    r.x = *reinterpret_cast<unsigned*>(&hi);
    r.y = *reinterpret_cast<unsigned*>(&lo);
    return r;
}

__device__ __forceinline__ int permkp(int kp) {
    return (kp >> 3) * 8 + (kp & 3) * 2 + ((kp >> 2) & 1);
}

__global__ void init_hidden_kernel(const float* __restrict__ hidden,
                                   float* __restrict__ h0, float* __restrict__ h1,
                                   uint2* __restrict__ p0, uint2* __restrict__ p1,
                                   unsigned* __restrict__ sync)
{
    int idx = blockIdx.x * blockDim.x + threadIdx.x;
    if (blockIdx.x == 0 && threadIdx.x < 8) sync[threadIdx.x] = 0u;
    const int n2 = Mm*Pp*Bb*256;
    if (idx >= n2) return;
    int mp  = idx / (Bb*256);
    int rem = idx % (Bb*256);
    int b  = rem >> 8;
    int kp = rem & 255;
    float2 v0 = *reinterpret_cast<const float2*>(&hidden[((size_t)mp*Ll + 0)*Bb*Hh + b*Hh + 2*kp]);
    float2 v1 = *reinterpret_cast<const float2*>(&hidden[((size_t)mp*Ll + 1)*Bb*Hh + b*Hh + 2*kp]);
    *reinterpret_cast<float2*>(&h0[((size_t)mp*Bb + b)*Hh + 2*kp]) = v0;
    *reinterpret_cast<float2*>(&h1[((size_t)mp*Bb + b)*Hh + 2*kp]) = v1;
    p0[((size_t)mp*Bb + b)*256 + permkp(kp)] = pack_hilo(v0.x, v0.y);
    p1[((size_t)mp*Bb + b)*256 + permkp(kp)] = pack_hilo(v1.x, v1.y);
}

__global__ void hidden_out_kernel(const float* __restrict__ h0, const float* __restrict__ h1,
                                  float* __restrict__ out)
{
    int idx = blockIdx.x * blockDim.x + threadIdx.x;
    const int n = Mm*Pp*Bb*Hh;
    if (idx >= n) return;
    int mp  = idx / (Bb*Hh);
    int rem = idx % (Bb*Hh);
    out[((size_t)mp*Ll + 0)*Bb*Hh + rem] = h0[idx];
    out[((size_t)mp*Ll + 1)*Bb*Hh + rem] = h1[idx];
}

__global__ void split_pack_kernel(const float* __restrict__ w0, const float* __restrict__ w1,
                                  uint2* __restrict__ outp)
{
    const int n = Mm * Gg * (Hh/2);
    int idx = blockIdx.x * blockDim.x + threadIdx.x;
    if (idx >= 2 * n) return;
    const float* src = (idx < n) ? w0 : w1;
    int within = (idx < n) ? idx : idx - n;
    float2 x = *reinterpret_cast<const float2*>(src + (size_t)within * 2);
    outp[idx] = pack_hilo(x.x, x.y);
}

__global__ __launch_bounds__(256) void gemm_tf32_bias(
    const float* __restrict__ A, long aStride,
    const float* __restrict__ W, long wStride,
    const float* __restrict__ bias, int bStride,
    float* __restrict__ C, long cStride,
    int rows, int N, int K)
{
    const int batch = blockIdx.z;
    A    += (long)batch * aStride;
    W    += (long)batch * wStride;
    bias += (long)batch * bStride;
    C    += (long)batch * cStride;

    const int r0 = blockIdx.y * 128;
    const int n0 = blockIdx.x * 64;

    __shared__ float As[128][36];
    __shared__ float Bs[64][36];

    const int tid  = threadIdx.x;
    const int lane = tid & 31;
    const int w    = tid >> 5;
    const int wr   = w >> 1;
    const int wc   = w & 1;
    const int gID  = lane >> 2;
    const int tig  = lane & 3;

    float c[2][4][4];
#pragma unroll
    for (int mi = 0; mi < 2; mi++)
#pragma unroll
        for (int ni = 0; ni < 4; ni++)
#pragma unroll
            for (int q = 0; q < 4; q++) c[mi][ni][q] = 0.f;

    for (int k0 = 0; k0 < K; k0 += 32) {
#pragma unroll
        for (int l = 0; l < 4; l++) {
            int f = tid + l * 256;
            int row = f >> 3;
            int kg  = f & 7;
            float4 v = *reinterpret_cast<const float4*>(&A[(long)(r0 + row) * K + k0 + kg * 4]);
            float4 t;
            t.x = tf32r(v.x); t.y = tf32r(v.y); t.z = tf32r(v.z); t.w = tf32r(v.w);
            *reinterpret_cast<float4*>(&As[row][kg * 4]) = t;
        }
#pragma unroll
        for (int l = 0; l < 2; l++) {
            int f = tid + l * 256;
            int col = f >> 3;
            int kg  = f & 7;
            float4 v = *reinterpret_cast<const float4*>(&W[(long)(n0 + col) * K + k0 + kg * 4]);
            float4 t;
            t.x = tf32r(v.x); t.y = tf32r(v.y); t.z = tf32r(v.z); t.w = tf32r(v.w);
            *reinterpret_cast<float4*>(&Bs[col][kg * 4]) = t;
        }
        __syncthreads();

#pragma unroll
        for (int k8 = 0; k8 < 4; k8++) {
            const int kb = k8 * 8;
            uint32_t af[2][4];
#pragma unroll
            for (int mi = 0; mi < 2; mi++) {
                int rb = wr * 32 + mi * 16 + gID;
                af[mi][0] = __float_as_uint(As[rb    ][kb + tig]);
                af[mi][1] = __float_as_uint(As[rb + 8][kb + tig]);
                af[mi][2] = __float_as_uint(As[rb    ][kb + 4 + tig]);
                af[mi][3] = __float_as_uint(As[rb + 8][kb + 4 + tig]);
            }
            uint32_t bf[4][2];
#pragma unroll
            for (int ni = 0; ni < 4; ni++) {
                int cb = wc * 32 + ni * 8 + gID;
                bf[ni][0] = __float_as_uint(Bs[cb][kb + tig]);
                bf[ni][1] = __float_as_uint(Bs[cb][kb + 4 + tig]);
            }
#pragma unroll
            for (int mi = 0; mi < 2; mi++)
#pragma unroll
                for (int ni = 0; ni < 4; ni++)
                    mma_tf32(c[mi][ni], af[mi], bf[ni]);
        }
        __syncthreads();
    }

#pragma unroll
    for (int mi = 0; mi < 2; mi++) {
#pragma unroll
        for (int ni = 0; ni < 4; ni++) {
            int row = r0 + wr * 32 + mi * 16 + gID;
            int col = n0 + wc * 32 + ni * 8 + 2 * tig;
            float b0 = bias[col], b1 = bias[col + 1];
            float2 v0 = make_float2(c[mi][ni][0] + b0, c[mi][ni][1] + b1);
            float2 v1 = make_float2(c[mi][ni][2] + b0, c[mi][ni][3] + b1);
            *reinterpret_cast<float2*>(&C[(long)row * N + col]) = v0;
            *reinterpret_cast<float2*>(&C[(long)(row + 8) * N + col]) = v1;
        }
    }
}

// ================= persistent GRU scan (round-10 base): deeper A ring, fast activations =================
// grid = 128 blocks (m = bx>>5, j0 = (bx&31)*16), 256 threads = 8 warps.
// warp w = rowgroup (16 rows), full K=512, 48 gate-cols of this j-slice.
template<int LAYER>
__global__ __launch_bounds__(256, 1) void gru_scan(
    float* __restrict__ bufA, float* __restrict__ bufB,
    uint2* __restrict__ pakA, uint2* __restrict__ pakB,
    const float* __restrict__ gi,
    const uint4* __restrict__ whp,
    const float* __restrict__ bhh,
    const float* __restrict__ dm,
    float* __restrict__ outact,
    unsigned* __restrict__ syncctr)
{
    extern __shared__ unsigned Wpk[];

    const int bx = blockIdx.x;
    const int m  = bx >> 5;
    const int j0 = (bx & 31) * 16;

    const int tid  = threadIdx.x;
    const int lane = tid & 31;
    const int w    = tid >> 5;
    const int g    = lane >> 2;
    const int tg   = lane & 3;

    {
        const uint4* wb = whp + (long)m * Gg * 128;
        for (int f = tid; f < 48 * 128; f += 256) {
            int cc = f >> 7, qq = f & 127;
            int gr = (cc >> 4) * Hh + j0 + (cc & 15);
            uint4 v = wb[(long)gr * 128 + qq];
            int kp0 = qq * 2;
            *reinterpret_cast<uint2*>(Wpk + cc * WSTRIDE + 2 * permkp(kp0))     = make_uint2(v.x, v.y);
            *reinterpret_cast<uint2*>(Wpk + cc * WSTRIDE + 2 * permkp(kp0 + 1)) = make_uint2(v.z, v.w);
        }
    }
    __syncthreads();

    const long hb  = (long)m * Rr * Hh;
    const long hb2 = (long)m * Rr * 256;
    const int  ar0 = w * 16 + g;
    const int  ar1 = w * 16 + 8 + g;

    float b_r[2][2], b_z[2][2], b_n[2][2];
#pragma unroll
    for (int u = 0; u < 2; u++)
#pragma unroll
        for (int jj = 0; jj < 2; jj++) {
            int j = j0 + u * 8 + 2 * tg + jj;
            b_r[u][jj] = __ldg(&bhh[m * Gg + j]);
            b_z[u][jj] = __ldg(&bhh[m * Gg + Hh + j]);
            b_n[u][jj] = __ldg(&bhh[m * Gg + 2 * Hh + j]);
        }

    float2 gr2[2][2], gz2[2][2], gn2[2][2], dm2[2][2];
    auto prefetch_gi = [&](int t) {
#pragma unroll
        for (int rh = 0; rh < 2; rh++) {
            int row = w * 16 + rh * 8 + g;
            int p = row >> 5, b = row & 31;
            long girow = (LAYER == 0)
                ? ((long)(m * Ss + t) * Bb + b) * Gg
                : ((long)((m * Pp + p) * Ss + t) * Bb + b) * Gg;
            long obase = (((long)(m * Pp + p) * Ss + t) * Bb + b) * Hh;
#pragma unroll
            for (int u = 0; u < 2; u++) {
                int j = j0 + u * 8 + 2 * tg;
                gr2[rh][u] = __ldcg(reinterpret_cast<const float2*>(&gi[girow + j]));
                gz2[rh][u] = __ldcg(reinterpret_cast<const float2*>(&gi[girow + Hh + j]));
                gn2[rh][u] = __ldcg(reinterpret_cast<const float2*>(&gi[girow + 2 * Hh + j]));
                if (LAYER == 0)
                    dm2[rh][u] = __ldcg(reinterpret_cast<const float2*>(&dm[obase + j]));
            }
        }
    };
    prefetch_gi(0);

    for (int t = 0; t < Ss; t++) {
        const float* hc = (t & 1) ? bufB : bufA;
        float*       hn = (t & 1) ? bufA : bufB;
        const uint2* pc = (t & 1) ? pakB : pakA;
        uint2*       pn = (t & 1) ? pakA : pakB;

        float2 ho2[2][2];
#pragma unroll
        for (int rh = 0; rh < 2; rh++) {
            int row = w * 16 + rh * 8 + g;
#pragma unroll
            for (int u = 0; u < 2; u++) {
                int j = j0 + u * 8 + 2 * tg;
                ho2[rh][u] = __ldcg(reinterpret_cast<const float2*>(&hc[hb + (long)row * Hh + j]));
            }
        }

        float cA[6][4], cB[6][4];
#pragma unroll
        for (int e = 0; e < 24; e++) { (&cA[0][0])[e] = 0.f; (&cB[0][0])[e] = 0.f; }

        auto fetchA = [&](int i, uint4* P) {
            P[0] = __ldcg(reinterpret_cast<const uint4*>(pc + hb2 + (long)ar0 * 256 + i * 8 + tg * 2));
            P[1] = __ldcg(reinterpret_cast<const uint4*>(pc + hb2 + (long)ar1 * 256 + i * 8 + tg * 2));
        };
        auto loadB = [&](int i, uint4* Bv) {
#pragma unroll
            for (int tI = 0; tI < 6; tI++)
                Bv[tI] = *reinterpret_cast<const uint4*>(Wpk + (tI * 8 + g) * WSTRIDE + i * 16 + tg * 4);
        };
        auto mmaI = [&](const uint4* P, const uint4* Bv) {
            uint32_t ahi[4] = {P[0].x, P[1].x, P[0].z, P[1].z};
            uint32_t alo[4] = {P[0].y, P[1].y, P[0].w, P[1].w};
#pragma unroll
            for (int tI = 0; tI < 6; tI++) {
                uint32_t bh[2] = {Bv[tI].x, Bv[tI].z};
                mma_bf16(cA[tI], ahi, bh);
            }
#pragma unroll
            for (int tI = 0; tI < 6; tI++) {
                uint32_t bl[2] = {Bv[tI].y, Bv[tI].w};
                mma_bf16(cB[tI], ahi, bl);
            }
#pragma unroll
            for (int tI = 0; tI < 6; tI++) {
                uint32_t bh[2] = {Bv[tI].x, Bv[tI].z};
                mma_bf16(cB[tI], alo, bh);
            }
        };

        // A ring depth 6 (prefetch distance 5); B ring depth 2
        uint4 P[6][2];
        uint4 Bf[2][6];
        fetchA(0, P[0]);
        fetchA(1, P[1]);
        fetchA(2, P[2]);
        fetchA(3, P[3]);
        fetchA(4, P[4]);
        loadB(0, Bf[0]);
#pragma unroll
        for (int i = 0; i < 32; i++) {
            if (i < 31) loadB(i + 1, Bf[(i + 1) & 1]);
            if (i < 27) fetchA(i + 5, P[(i + 5) % 6]);
            mmaI(P[i % 6], Bf[i & 1]);
        }

        // ---- epilogue: gates + h update ----
#pragma unroll
        for (int rh = 0; rh < 2; rh++) {
            int row = w * 16 + rh * 8 + g;
            int p = row >> 5, b = row & 31;
            long obase = (((long)(m * Pp + p) * Ss + t) * Bb + b) * Hh;
            uint2 pk[2];
#pragma unroll
            for (int u = 0; u < 2; u++) {
                int j = j0 + u * 8 + 2 * tg;
                float hv[2];
#pragma unroll
                for (int jj = 0; jj < 2; jj++) {
                    int qi = rh * 2 + jj;
                    float ghr = cA[0 + u][qi] + cB[0 + u][qi] + b_r[u][jj];
                    float ghz = cA[2 + u][qi] + cB[2 + u][qi] + b_z[u][jj];
                    float ghn = cA[4 + u][qi] + cB[4 + u][qi] + b_n[u][jj];
                    float gih = (jj == 0) ? gr2[rh][u].x : gr2[rh][u].y;
                    float giz = (jj == 0) ? gz2[rh][u].x : gz2[rh][u].y;
                    float gin = (jj == 0) ? gn2[rh][u].x : gn2[rh][u].y;
                    float hold = (jj == 0) ? ho2[rh][u].x : ho2[rh][u].y;
                    float rg = fast_sigmoid(gih + ghr);
                    float zg = fast_sigmoid(giz + ghz);
                    float ng = fast_tanh(gin + rg * ghn);
                    hv[jj] = (1.0f - zg) * ng + zg * hold;
                }
                __stcg(reinterpret_cast<float2*>(&hn[hb + (long)row * Hh + j]),
                       make_float2(hv[0], hv[1]));
                pk[u] = pack_hilo(hv[0], hv[1]);
                float2 oa;
                if (LAYER == 0) {
                    oa = make_float2(hv[0] * dm2[rh][u].x, hv[1] * dm2[rh][u].y);
                } else {
                    oa = make_float2(fmaxf(hv[0], 0.f) + 0.01f * fminf(hv[0], 0.f),
                                     fmaxf(hv[1], 0.f) + 0.01f * fminf(hv[1], 0.f));
                }
                __stcg(reinterpret_cast<float2*>(&outact[obase + j]), oa);
            }
            __stcg(reinterpret_cast<uint4*>(pn + hb2 + (long)row * 256 + (j0 >> 1) + tg * 2),
                   make_uint4(pk[0].x, pk[0].y, pk[1].x, pk[1].y));
        }

        if (t + 1 < Ss) prefetch_gi(t + 1);

        // ---- per-model grid barrier (atomic + pure spin) ----
        __syncthreads();
        if (tid == 0) {
            __threadfence();
            atomicAdd(&syncctr[m], 1u);
            unsigned target = 32u * (unsigned)(t + 1);
            volatile unsigned* vc = (volatile unsigned*)&syncctr[m];
            while (*vc < target) { }
        }
        __syncthreads();
    }
}

__global__ void meanvar_kernel(const float* __restrict__ preds,
                               float* __restrict__ out_mean, float* __restrict__ out_var)
{
    const int n = Ss * Bb * Oo;
    int idx = blockIdx.x * blockDim.x + threadIdx.x;
    if (idx >= n) return;
    float v[16];
    float s = 0.f;
#pragma unroll
    for (int mp = 0; mp < 16; mp++) {
        v[mp] = preds[(long)mp * n + idx];
        s += v[mp];
    }
    float mu = s * (1.0f / 16.0f);
    float qq = 0.f;
#pragma unroll
    for (int mp = 0; mp < 16; mp++) {
        float d = v[mp] - mu;
        qq += d * d;
    }
    out_mean[idx] = mu;
    out_var[idx]  = qq * (1.0f / 15.0f);
}

extern "C" void kernel_launch(void* const* d_in, const int* in_sizes, int n_in,
                              void* d_out, int out_size)
{
    const float* input  = (const float*)d_in[0];
    const float* hidden = (const float*)d_in[1];
    const float* w_ih0  = (const float*)d_in[2];
    const float* w_hh0  = (const float*)d_in[3];
    const float* b_ih0  = (const float*)d_in[4];
    const float* b_hh0  = (const float*)d_in[5];
    const float* w_ih1  = (const float*)d_in[6];
    const float* w_hh1  = (const float*)d_in[7];
    const float* b_ih1  = (const float*)d_in[8];
    const float* b_hh1  = (const float*)d_in[9];
    const float* lin_w  = (const float*)d_in[10];
    const float* lin_b  = (const float*)d_in[11];
    const float* dm     = (const float*)d_in[12];

    float* out = (float*)d_out;
    float* out_mean   = out;
    float* out_var    = out + (size_t)Ss * Bb * Oo;
    float* preds      = out + 2 * (size_t)Ss * Bb * Oo;
    float* hidden_out = preds + (size_t)Mm * Pp * Ss * Bb * Oo;

    float *gi0, *y0m, *gi1, *a1, *h0a, *h0b, *h1a, *h1b;
    uint4 *p0a, *p0b, *p1a, *p1b, *whp;
    unsigned* syncp;
    cudaGetSymbolAddress((void**)&gi0, g_gi0);
    cudaGetSymbolAddress((void**)&y0m, g_y0m);
    cudaGetSymbolAddress((void**)&gi1, g_gi1);
    cudaGetSymbolAddress((void**)&a1,  g_a1);
    cudaGetSymbolAddress((void**)&h0a, g_h0a);
    cudaGetSymbolAddress((void**)&h0b, g_h0b);
    cudaGetSymbolAddress((void**)&h1a, g_h1a);
    cudaGetSymbolAddress((void**)&h1b, g_h1b);
    cudaGetSymbolAddress((void**)&p0a, g_hp0a);
    cudaGetSymbolAddress((void**)&p0b, g_hp0b);
    cudaGetSymbolAddress((void**)&p1a, g_hp1a);
    cudaGetSymbolAddress((void**)&p1b, g_hp1b);
    cudaGetSymbolAddress((void**)&whp, g_whhp);
    cudaGetSymbolAddress((void**)&syncp, g_sync);

    cudaFuncSetAttribute(gru_scan<0>, cudaFuncAttributeMaxDynamicSharedMemorySize, SCAN_SMEM_BYTES);
    cudaFuncSetAttribute(gru_scan<1>, cudaFuncAttributeMaxDynamicSharedMemorySize, SCAN_SMEM_BYTES);

    {
        int n2 = 2 * Mm * Gg * (Hh / 2);
        split_pack_kernel<<<(n2 + 255) / 256, 256>>>(w_hh0, w_hh1, (uint2*)whp);
    }
    {
        int n2 = Mm * Pp * Bb * 256;
        init_hidden_kernel<<<(n2 + 255) / 256, 256>>>(hidden, h0a, h1a,
                                                      (uint2*)p0a, (uint2*)p1a, syncp);
    }
    {
        dim3 grid(Gg / 64, (Ss * Bb) / 128, Mm);
        gemm_tf32_bias<<<grid, 256>>>(input, 0L,
                                      w_ih0, (long)Gg * Ii,
                                      b_ih0, Gg,
                                      gi0, (long)Ss * Bb * Gg,
                                      Ss * Bb, Gg, Ii);
    }

    gru_scan<0><<<128, 256, SCAN_SMEM_BYTES>>>(h0a, h0b, (uint2*)p0a, (uint2*)p0b, gi0,
                                               whp, b_hh0, dm, y0m, syncp);

    {
        dim3 grid(Gg / 64, (Pp * Ss * Bb) / 128, Mm);
        gemm_tf32_bias<<<grid, 256>>>(y0m, (long)Pp * Ss * Bb * Hh,
                                      w_ih1, (long)Gg * Hh,
                                      b_ih1, Gg,
                                      gi1, (long)Pp * Ss * Bb * Gg,
                                      Pp * Ss * Bb, Gg, Hh);
    }

    gru_scan<1><<<128, 256, SCAN_SMEM_BYTES>>>(h1a, h1b, (uint2*)p1a, (uint2*)p1b, gi1,
                                               whp + (long)Mm * Gg * 128, b_hh1,
                                               nullptr, a1, syncp + 4);

    {
        dim3 grid(Oo / 64, (Pp * Ss * Bb) / 128, Mm);
        gemm_tf32_bias<<<grid, 256>>>(a1, (long)Pp * Ss * Bb * Hh,
                                      lin_w, (long)Oo * Hh,
                                      lin_b, Oo,
                                      preds, (long)Pp * Ss * Bb * Oo,
                                      Pp * Ss * Bb, Oo, Hh);
    }

    meanvar_kernel<<<(Ss * Bb * Oo + 255) / 256, 256>>>(preds, out_mean, out_var);
    hidden_out_kernel<<<(Mm*Pp*Bb*Hh + 255) / 256, 256>>>(h0a, h1a, hidden_out);
}

// round 13
// speedup vs baseline: 1.1968x; 1.1968x over previous
#include <cuda_runtime.h>
#include <cuda_bf16.h>
#include <cuda_fp16.h>
#include <math.h>
#include <stdint.h>

#define Mm 4
#define Pp 4
#define Ll 2
#define Ss 256
#define Bb 32
#define Ii 256
#define Hh 512
#define Oo 256
#define Gg (3*Hh)
#define Rr (Pp*Bb)

#define WST2 272                         // smem words per gate-col row (256 + 16 pad; 272%32==16 -> conflict-free LDS.128)
#define SCAN_SMEM_BYTES (48*WST2*4)      // 52224

__device__ float g_gi0[(size_t)Mm*Ss*Bb*Gg];
__device__ float g_y0m[(size_t)Mm*Pp*Ss*Bb*Hh];
__device__ float g_gi1[(size_t)Mm*Pp*Ss*Bb*Gg];
__device__ float g_a1 [(size_t)Mm*Pp*Ss*Bb*Hh];
__device__ float g_h0a[Mm*Rr*Hh];
__device__ float g_h0b[Mm*Rr*Hh];
__device__ float g_h1a[Mm*Rr*Hh];
__device__ float g_h1b[Mm*Rr*Hh];
// packed fp16 (hi,lo) h, PERMUTED fragment layout, double buffered
__device__ uint4 g_hp0a[Mm*Rr*128];
__device__ uint4 g_hp0b[Mm*Rr*128];
__device__ uint4 g_hp1a[Mm*Rr*128];
__device__ uint4 g_hp1b[Mm*Rr*128];
// single-fp16 recurrent weights: [layer][Mm][3H] rows x 256 fp16x2 words
__device__ uint4 g_whf4[2 * Mm * Gg * 64];
__device__ unsigned g_sync[8];

__device__ __forceinline__ float tf32r(float x) {
    uint32_t u;
    asm("cvt.rna.tf32.f32 %0, %1;" : "=r"(u) : "f"(x));
    return __uint_as_float(u);
}

__device__ __forceinline__ void mma_tf32(float c[4], const uint32_t a[4], const uint32_t b[2]) {
    asm volatile(
        "mma.sync.aligned.m16n8k8.row.col.f32.tf32.tf32.f32 "
        "{%0,%1,%2,%3},{%4,%5,%6,%7},{%8,%9},{%0,%1,%2,%3};"
        : "+f"(c[0]), "+f"(c[1]), "+f"(c[2]), "+f"(c[3])
        : "r"(a[0]), "r"(a[1]), "r"(a[2]), "r"(a[3]), "r"(b[0]), "r"(b[1]));
}

__device__ __forceinline__ void mma_f16(float c[4], const uint32_t a[4], const uint32_t b[2]) {
    asm volatile(
        "mma.sync.aligned.m16n8k16.row.col.f32.f16.f16.f32 "
        "{%0,%1,%2,%3},{%4,%5,%6,%7},{%8,%9},{%0,%1,%2,%3};"
        : "+f"(c[0]), "+f"(c[1]), "+f"(c[2]), "+f"(c[3])
        : "r"(a[0]), "r"(a[1]), "r"(a[2]), "r"(a[3]), "r"(b[0]), "r"(b[1]));
}

__device__ __forceinline__ float sigmoidf_(float x) { return 1.0f / (1.0f + expf(-x)); }

// pack two fp32 into (fp16-hi pair word, fp16-lo pair word)
__device__ __forceinline__ uint2 pack_hilo(float x0, float x1) {
    __half2 hi = __floats2half2_rn(x0, x1);
    float l0 = x0 - __half2float(__low2half(hi));
    float l1 = x1 - __half2float(__high2half(hi));
    __half2 lo = __floats2half2_rn(l0, l1);
    uint2 r;
    r.x = *reinterpret_cast<unsigned*>(&hi);
    r.y = *reinterpret_cast<unsigned*>(&lo);
    return r;
}

// fragment permutation of k-pair index for the packed-h (A) layout
__device__ __forceinline__ int permkp(int kp) {
    return (kp >> 3) * 8 + (kp & 3) * 2 + ((kp >> 2) & 1);
}
// W smem permutation: supergroup of 16 kp = 2 k16-groups; uint4 at sg*16+tg*4 holds
// [grp0 b0, grp0 b1, grp1 b0, grp1 b1] for that tg.
__device__ __forceinline__ int permw(int kp) {
    int sg = kp >> 4;
    int rr = kp & 7;
    int grp = (kp >> 3) & 1;
    return sg * 16 + (rr & 3) * 4 + grp * 2 + (rr >> 2);
}

__global__ void init_hidden_kernel(const float* __restrict__ hidden,
                                   float* __restrict__ h0, float* __restrict__ h1,
                                   uint2* __restrict__ p0, uint2* __restrict__ p1,
                                   unsigned* __restrict__ sync)
{
    int idx = blockIdx.x * blockDim.x + threadIdx.x;
    if (blockIdx.x == 0 && threadIdx.x < 8) sync[threadIdx.x] = 0u;
    const int n2 = Mm*Pp*Bb*256;
    if (idx >= n2) return;
    int mp  = idx / (Bb*256);
    int rem = idx % (Bb*256);
    int b  = rem >> 8;
    int kp = rem & 255;
    float2 v0 = *reinterpret_cast<const float2*>(&hidden[((size_t)mp*Ll + 0)*Bb*Hh + b*Hh + 2*kp]);
    float2 v1 = *reinterpret_cast<const float2*>(&hidden[((size_t)mp*Ll + 1)*Bb*Hh + b*Hh + 2*kp]);
    *reinterpret_cast<float2*>(&h0[((size_t)mp*Bb + b)*Hh + 2*kp]) = v0;
    *reinterpret_cast<float2*>(&h1[((size_t)mp*Bb + b)*Hh + 2*kp]) = v1;
    p0[((size_t)mp*Bb + b)*256 + permkp(kp)] = pack_hilo(v0.x, v0.y);
    p1[((size_t)mp*Bb + b)*256 + permkp(kp)] = pack_hilo(v1.x, v1.y);
}

__global__ void hidden_out_kernel(const float* __restrict__ h0, const float* __restrict__ h1,
                                  float* __restrict__ out)
{
    int idx = blockIdx.x * blockDim.x + threadIdx.x;
    const int n = Mm*Pp*Bb*Hh;
    if (idx >= n) return;
    int mp  = idx / (Bb*Hh);
    int rem = idx % (Bb*Hh);
    out[((size_t)mp*Ll + 0)*Bb*Hh + rem] = h0[idx];
    out[((size_t)mp*Ll + 1)*Bb*Hh + rem] = h1[idx];
}

// split recurrent weights into single-fp16 pair words
__global__ void split_w16_kernel(const float* __restrict__ w0, const float* __restrict__ w1,
                                 unsigned* __restrict__ outp)
{
    const int n = Mm * Gg * 256;   // fp16x2 words per layer
    int idx = blockIdx.x * blockDim.x + threadIdx.x;
    if (idx >= 2 * n) return;
    const float* src = (idx < n) ? w0 : w1;
    int wi = (idx < n) ? idx : idx - n;
    float2 x = *reinterpret_cast<const float2*>(src + (size_t)wi * 2);
    __half2 h = __floats2half2_rn(x.x, x.y);
    outp[idx] = *reinterpret_cast<unsigned*>(&h);
}

__global__ __launch_bounds__(256) void gemm_tf32_bias(
    const float* __restrict__ A, long aStride,
    const float* __restrict__ W, long wStride,
    const float* __restrict__ bias, int bStride,
    float* __restrict__ C, long cStride,
    int rows, int N, int K)
{
    const int batch = blockIdx.z;
    A    += (long)batch * aStride;
    W    += (long)batch * wStride;
    bias += (long)batch * bStride;
    C    += (long)batch * cStride;

    const int r0 = blockIdx.y * 128;
    const int n0 = blockIdx.x * 64;

    __shared__ float As[128][36];
    __shared__ float Bs[64][36];

    const int tid  = threadIdx.x;
    const int lane = tid & 31;
    const int w    = tid >> 5;
    const int wr   = w >> 1;
    const int wc   = w & 1;
    const int gID  = lane >> 2;
    const int tig  = lane & 3;

    float c[2][4][4];
#pragma unroll
    for (int mi = 0; mi < 2; mi++)
#pragma unroll
        for (int ni = 0; ni < 4; ni++)
#pragma unroll
            for (int q = 0; q < 4; q++) c[mi][ni][q] = 0.f;

    for (int k0 = 0; k0 < K; k0 += 32) {
#pragma unroll
        for (int l = 0; l < 4; l++) {
            int f = tid + l * 256;
            int row = f >> 3;
            int kg  = f & 7;
            float4 v = *reinterpret_cast<const float4*>(&A[(long)(r0 + row) * K + k0 + kg * 4]);
            float4 t;
            t.x = tf32r(v.x); t.y = tf32r(v.y); t.z = tf32r(v.z); t.w = tf32r(v.w);
            *reinterpret_cast<float4*>(&As[row][kg * 4]) = t;
        }
#pragma unroll
        for (int l = 0; l < 2; l++) {
            int f = tid + l * 256;
            int col = f >> 3;
            int kg  = f & 7;
            float4 v = *reinterpret_cast<const float4*>(&W[(long)(n0 + col) * K + k0 + kg * 4]);
            float4 t;
            t.x = tf32r(v.x); t.y = tf32r(v.y); t.z = tf32r(v.z); t.w = tf32r(v.w);
            *reinterpret_cast<float4*>(&Bs[col][kg * 4]) = t;
        }
        __syncthreads();

#pragma unroll
        for (int k8 = 0; k8 < 4; k8++) {
            const int kb = k8 * 8;
            uint32_t af[2][4];
#pragma unroll
            for (int mi = 0; mi < 2; mi++) {
                int rb = wr * 32 + mi * 16 + gID;
                af[mi][0] = __float_as_uint(As[rb    ][kb + tig]);
                af[mi][1] = __float_as_uint(As[rb + 8][kb + tig]);
                af[mi][2] = __float_as_uint(As[rb    ][kb + 4 + tig]);
                af[mi][3] = __float_as_uint(As[rb + 8][kb + 4 + tig]);
            }
            uint32_t bf[4][2];
#pragma unroll
            for (int ni = 0; ni < 4; ni++) {
                int cb = wc * 32 + ni * 8 + gID;
                bf[ni][0] = __float_as_uint(Bs[cb][kb + tig]);
                bf[ni][1] = __float_as_uint(Bs[cb][kb + 4 + tig]);
            }
#pragma unroll
            for (int mi = 0; mi < 2; mi++)
#pragma unroll
                for (int ni = 0; ni < 4; ni++)
                    mma_tf32(c[mi][ni], af[mi], bf[ni]);
        }
        __syncthreads();
    }

#pragma unroll
    for (int mi = 0; mi < 2; mi++) {
#pragma unroll
        for (int ni = 0; ni < 4; ni++) {
            int row = r0 + wr * 32 + mi * 16 + gID;
            int col = n0 + wc * 32 + ni * 8 + 2 * tig;
            float b0 = bias[col], b1 = bias[col + 1];
            float2 v0 = make_float2(c[mi][ni][0] + b0, c[mi][ni][1] + b1);
            float2 v1 = make_float2(c[mi][ni][2] + b0, c[mi][ni][3] + b1);
            *reinterpret_cast<float2*>(&C[(long)row * N + col]) = v0;
            *reinterpret_cast<float2*>(&C[(long)(row + 8) * N + col]) = v1;
        }
    }
}

// ================= persistent GRU scan: fp16 2-term (W single-fp16, h hi/lo fp16) =================
// grid = 128 blocks (m = bx>>5, j0 = (bx&31)*16), 256 threads = 8 warps.
// warp w = rowgroup (16 rows), full K=512, 48 gate-cols of this j-slice.
template<int LAYER>
__global__ __launch_bounds__(256, 1) void gru_scan(
    float* __restrict__ bufA, float* __restrict__ bufB,
    uint2* __restrict__ pakA, uint2* __restrict__ pakB,
    const float* __restrict__ gi,
    const uint4* __restrict__ whf4,
    const float* __restrict__ bhh,
    const float* __restrict__ dm,
    float* __restrict__ outact,
    unsigned* __restrict__ syncctr)
{
    extern __shared__ unsigned Wpk[];

    const int bx = blockIdx.x;
    const int m  = bx >> 5;
    const int j0 = (bx & 31) * 16;

    const int tid  = threadIdx.x;
    const int lane = tid & 31;
    const int w    = tid >> 5;
    const int g    = lane >> 2;
    const int tg   = lane & 3;

    // load single-fp16 weights into smem, W-permuted (3072 uint4 loads total)
    {
        const uint4* wb = whf4 + (long)m * Gg * 64;
        for (int f = tid; f < 48 * 64; f += 256) {
            int cc = f >> 6, q = f & 63;
            int gr = (cc >> 4) * Hh + j0 + (cc & 15);
            uint4 v = wb[(long)gr * 64 + q];
            unsigned wv[4] = {v.x, v.y, v.z, v.w};
#pragma unroll
            for (int e = 0; e < 4; e++)
                Wpk[cc * WST2 + permw(q * 4 + e)] = wv[e];
        }
    }
    __syncthreads();

    const long hb  = (long)m * Rr * Hh;
    const long hb2 = (long)m * Rr * 256;
    const int  ar0 = w * 16 + g;
    const int  ar1 = w * 16 + 8 + g;

    float b_r[2][2], b_z[2][2], b_n[2][2];
#pragma unroll
    for (int u = 0; u < 2; u++)
#pragma unroll
        for (int jj = 0; jj < 2; jj++) {
            int j = j0 + u * 8 + 2 * tg + jj;
            b_r[u][jj] = __ldg(&bhh[m * Gg + j]);
            b_z[u][jj] = __ldg(&bhh[m * Gg + Hh + j]);
            b_n[u][jj] = __ldg(&bhh[m * Gg + 2 * Hh + j]);
        }

    float2 gr2[2][2], gz2[2][2], gn2[2][2], dm2[2][2];
    auto prefetch_gi = [&](int t) {
#pragma unroll
        for (int rh = 0; rh < 2; rh++) {
            int row = w * 16 + rh * 8 + g;
            int p = row >> 5, b = row & 31;
            long girow = (LAYER == 0)
                ? ((long)(m * Ss + t) * Bb + b) * Gg
                : ((long)((m * Pp + p) * Ss + t) * Bb + b) * Gg;
            long obase = (((long)(m * Pp + p) * Ss + t) * Bb + b) * Hh;
#pragma unroll
            for (int u = 0; u < 2; u++) {
                int j = j0 + u * 8 + 2 * tg;
                gr2[rh][u] = __ldcg(reinterpret_cast<const float2*>(&gi[girow + j]));
                gz2[rh][u] = __ldcg(reinterpret_cast<const float2*>(&gi[girow + Hh + j]));
                gn2[rh][u] = __ldcg(reinterpret_cast<const float2*>(&gi[girow + 2 * Hh + j]));
                if (LAYER == 0)
                    dm2[rh][u] = __ldcg(reinterpret_cast<const float2*>(&dm[obase + j]));
            }
        }
    };
    prefetch_gi(0);

    for (int t = 0; t < Ss; t++) {
        const float* hc = (t & 1) ? bufB : bufA;
        float*       hn = (t & 1) ? bufA : bufB;
        const uint2* pc = (t & 1) ? pakB : pakA;
        uint2*       pn = (t & 1) ? pakA : pakB;

        float2 ho2[2][2];
#pragma unroll
        for (int rh = 0; rh < 2; rh++) {
            int row = w * 16 + rh * 8 + g;
#pragma unroll
            for (int u = 0; u < 2; u++) {
                int j = j0 + u * 8 + 2 * tg;
                ho2[rh][u] = __ldcg(reinterpret_cast<const float2*>(&hc[hb + (long)row * Hh + j]));
            }
        }

        float cA[6][4], cB[6][4];
#pragma unroll
        for (int e = 0; e < 24; e++) { (&cA[0][0])[e] = 0.f; (&cB[0][0])[e] = 0.f; }

        auto fetchA = [&](int i, uint4* P) {
            P[0] = __ldcg(reinterpret_cast<const uint4*>(pc + hb2 + (long)ar0 * 256 + i * 8 + tg * 2));
            P[1] = __ldcg(reinterpret_cast<const uint4*>(pc + hb2 + (long)ar1 * 256 + i * 8 + tg * 2));
        };
        auto loadBpair = [&](int p, uint4* Bq) {
#pragma unroll
            for (int tI = 0; tI < 6; tI++)
                Bq[tI] = *reinterpret_cast<const uint4*>(Wpk + (tI * 8 + g) * WST2 + p * 16 + tg * 4);
        };
        auto mmaI = [&](const uint4* P, const uint4* Bq, int sel) {
            uint32_t ahi[4] = {P[0].x, P[1].x, P[0].z, P[1].z};
            uint32_t alo[4] = {P[0].y, P[1].y, P[0].w, P[1].w};
#pragma unroll
            for (int tI = 0; tI < 6; tI++) {
                uint32_t bh[2];
                bh[0] = sel ? Bq[tI].z : Bq[tI].x;
                bh[1] = sel ? Bq[tI].w : Bq[tI].y;
                mma_f16(cA[tI], ahi, bh);
            }
#pragma unroll
            for (int tI = 0; tI < 6; tI++) {
                uint32_t bh[2];
                bh[0] = sel ? Bq[tI].z : Bq[tI].x;
                bh[1] = sel ? Bq[tI].w : Bq[tI].y;
                mma_f16(cB[tI], alo, bh);
            }
        };

        uint4 P[4][2];
        uint4 Bq[2][6];
        fetchA(0, P[0]);
        fetchA(1, P[1]);
        fetchA(2, P[2]);
        loadBpair(0, Bq[0]);
#pragma unroll
        for (int p = 0; p < 16; p++) {
            if (p < 15) loadBpair(p + 1, Bq[(p + 1) & 1]);
            int i0 = 2 * p, i1 = 2 * p + 1;
            if (i0 + 3 < 32) fetchA(i0 + 3, P[(i0 + 3) & 3]);
            mmaI(P[i0 & 3], Bq[p & 1], 0);
            if (i1 + 3 < 32) fetchA(i1 + 3, P[(i1 + 3) & 3]);
            mmaI(P[i1 & 3], Bq[p & 1], 1);
        }

        // ---- epilogue: gates + h update ----
#pragma unroll
        for (int rh = 0; rh < 2; rh++) {
            int row = w * 16 + rh * 8 + g;
            int p = row >> 5, b = row & 31;
            long obase = (((long)(m * Pp + p) * Ss + t) * Bb + b) * Hh;
            uint2 pk[2];
#pragma unroll
            for (int u = 0; u < 2; u++) {
                int j = j0 + u * 8 + 2 * tg;
                float hv[2];
#pragma unroll
                for (int jj = 0; jj < 2; jj++) {
                    int qi = rh * 2 + jj;
                    float ghr = cA[0 + u][qi] + cB[0 + u][qi] + b_r[u][jj];
                    float ghz = cA[2 + u][qi] + cB[2 + u][qi] + b_z[u][jj];
                    float ghn = cA[4 + u][qi] + cB[4 + u][qi] + b_n[u][jj];
                    float gih = (jj == 0) ? gr2[rh][u].x : gr2[rh][u].y;
                    float giz = (jj == 0) ? gz2[rh][u].x : gz2[rh][u].y;
                    float gin = (jj == 0) ? gn2[rh][u].x : gn2[rh][u].y;
                    float hold = (jj == 0) ? ho2[rh][u].x : ho2[rh][u].y;
                    float rg = sigmoidf_(gih + ghr);
                    float zg = sigmoidf_(giz + ghz);
                    float ng = tanhf(gin + rg * ghn);
                    hv[jj] = (1.0f - zg) * ng + zg * hold;
                }
                __stcg(reinterpret_cast<float2*>(&hn[hb + (long)row * Hh + j]),
                       make_float2(hv[0], hv[1]));
                pk[u] = pack_hilo(hv[0], hv[1]);
                float2 oa;
                if (LAYER == 0) {
                    oa = make_float2(hv[0] * dm2[rh][u].x, hv[1] * dm2[rh][u].y);
                } else {
                    oa = make_float2(fmaxf(hv[0], 0.f) + 0.01f * fminf(hv[0], 0.f),
                                     fmaxf(hv[1], 0.f) + 0.01f * fminf(hv[1], 0.f));
                }
                __stcg(reinterpret_cast<float2*>(&outact[obase + j]), oa);
            }
            __stcg(reinterpret_cast<uint4*>(pn + hb2 + (long)row * 256 + (j0 >> 1) + tg * 2),
                   make_uint4(pk[0].x, pk[0].y, pk[1].x, pk[1].y));
        }

        if (t + 1 < Ss) prefetch_gi(t + 1);

        // ---- per-model grid barrier (round-10 form) ----
        __syncthreads();
        if (tid == 0) {
            __threadfence();
            atomicAdd(&syncctr[m], 1u);
            unsigned target = 32u * (unsigned)(t + 1);
            volatile unsigned* vc = (volatile unsigned*)&syncctr[m];
            while (*vc < target) __nanosleep(32);
        }
        __syncthreads();
    }
}

__global__ void meanvar_kernel(const float* __restrict__ preds,
                               float* __restrict__ out_mean, float* __restrict__ out_var)
{
    const int n = Ss * Bb * Oo;
    int idx = blockIdx.x * blockDim.x + threadIdx.x;
    if (idx >= n) return;
    float v[16];
    float s = 0.f;
#pragma unroll
    for (int mp = 0; mp < 16; mp++) {
        v[mp] = preds[(long)mp * n + idx];
        s += v[mp];
    }
    float mu = s * (1.0f / 16.0f);
    float qq = 0.f;
#pragma unroll
    for (int mp = 0; mp < 16; mp++) {
        float d = v[mp] - mu;
        qq += d * d;
    }
    out_mean[idx] = mu;
    out_var[idx]  = qq * (1.0f / 15.0f);
}

extern "C" void kernel_launch(void* const* d_in, const int* in_sizes, int n_in,
                              void* d_out, int out_size)
{
    const float* input  = (const float*)d_in[0];
    const float* hidden = (const float*)d_in[1];
    const float* w_ih0  = (const float*)d_in[2];
    const float* w_hh0  = (const float*)d_in[3];
    const float* b_ih0  = (const float*)d_in[4];
    const float* b_hh0  = (const float*)d_in[5];
    const float* w_ih1  = (const float*)d_in[6];
    const float* w_hh1  = (const float*)d_in[7];
    const float* b_ih1  = (const float*)d_in[8];
    const float* b_hh1  = (const float*)d_in[9];
    const float* lin_w  = (const float*)d_in[10];
    const float* lin_b  = (const float*)d_in[11];
    const float* dm     = (const float*)d_in[12];

    float* out = (float*)d_out;
    float* out_mean   = out;
    float* out_var    = out + (size_t)Ss * Bb * Oo;
    float* preds      = out + 2 * (size_t)Ss * Bb * Oo;
    float* hidden_out = preds + (size_t)Mm * Pp * Ss * Bb * Oo;

    float *gi0, *y0m, *gi1, *a1, *h0a, *h0b, *h1a, *h1b;
    uint4 *p0a, *p0b, *p1a, *p1b, *whf4;
    unsigned* syncp;
    cudaGetSymbolAddress((void**)&gi0, g_gi0);
    cudaGetSymbolAddress((void**)&y0m, g_y0m);
    cudaGetSymbolAddress((void**)&gi1, g_gi1);
    cudaGetSymbolAddress((void**)&a1,  g_a1);
    cudaGetSymbolAddress((void**)&h0a, g_h0a);
    cudaGetSymbolAddress((void**)&h0b, g_h0b);
    cudaGetSymbolAddress((void**)&h1a, g_h1a);
    cudaGetSymbolAddress((void**)&h1b, g_h1b);
    cudaGetSymbolAddress((void**)&p0a, g_hp0a);
    cudaGetSymbolAddress((void**)&p0b, g_hp0b);
    cudaGetSymbolAddress((void**)&p1a, g_hp1a);
    cudaGetSymbolAddress((void**)&p1b, g_hp1b);
    cudaGetSymbolAddress((void**)&whf4, g_whf4);
    cudaGetSymbolAddress((void**)&syncp, g_sync);

    cudaFuncSetAttribute(gru_scan<0>, cudaFuncAttributeMaxDynamicSharedMemorySize, SCAN_SMEM_BYTES);
    cudaFuncSetAttribute(gru_scan<1>, cudaFuncAttributeMaxDynamicSharedMemorySize, SCAN_SMEM_BYTES);

    {
        int n2 = 2 * Mm * Gg * 256;
        split_w16_kernel<<<(n2 + 255) / 256, 256>>>(w_hh0, w_hh1, (unsigned*)whf4);
    }
    {
        int n2 = Mm * Pp * Bb * 256;
        init_hidden_kernel<<<(n2 + 255) / 256, 256>>>(hidden, h0a, h1a,
                                                      (uint2*)p0a, (uint2*)p1a, syncp);
    }
    {
        dim3 grid(Gg / 64, (Ss * Bb) / 128, Mm);
        gemm_tf32_bias<<<grid, 256>>>(input, 0L,
                                      w_ih0, (long)Gg * Ii,
                                      b_ih0, Gg,
                                      gi0, (long)Ss * Bb * Gg,
                                      Ss * Bb, Gg, Ii);
    }

    gru_scan<0><<<128, 256, SCAN_SMEM_BYTES>>>(h0a, h0b, (uint2*)p0a, (uint2*)p0b, gi0,
                                               whf4, b_hh0, dm, y0m, syncp);

    {
        dim3 grid(Gg / 64, (Pp * Ss * Bb) / 128, Mm);
        gemm_tf32_bias<<<grid, 256>>>(y0m, (long)Pp * Ss * Bb * Hh,
                                      w_ih1, (long)Gg * Hh,
                                      b_ih1, Gg,
                                      gi1, (long)Pp * Ss * Bb * Gg,
                                      Pp * Ss * Bb, Gg, Hh);
    }

    gru_scan<1><<<128, 256, SCAN_SMEM_BYTES>>>(h1a, h1b, (uint2*)p1a, (uint2*)p1b, gi1,
                                               whf4 + (long)Mm * Gg * 64, b_hh1,
                                               nullptr, a1, syncp + 4);

    {
        dim3 grid(Oo / 64, (Pp * Ss * Bb) / 128, Mm);
        gemm_tf32_bias<<<grid, 256>>>(a1, (long)Pp * Ss * Bb * Hh,
                                      lin_w, (long)Oo * Hh,
                                      lin_b, Oo,
                                      preds, (long)Pp * Ss * Bb * Oo,
                                      Pp * Ss * Bb, Oo, Hh);
    }

    meanvar_kernel<<<(Ss * Bb * Oo + 255) / 256, 256>>>(preds, out_mean, out_var);
    hidden_out_kernel<<<(Mm*Pp*Bb*Hh + 255) / 256, 256>>>(h0a, h1a, hidden_out);
}

// round 14
// speedup vs baseline: 1.4425x; 1.2053x over previous
#include <cuda_runtime.h>
#include <cuda_bf16.h>
#include <cuda_fp16.h>
#include <math.h>
#include <stdint.h>

#define Mm 4
#define Pp 4
#define Ll 2
#define Ss 256
#define Bb 32
#define Ii 256
#define Hh 512
#define Oo 256
#define Gg (3*Hh)
#define Rr (Pp*Bb)

#define WST2 272                         // smem words per gate-col row (256 + 16 pad)
#define SCAN_SMEM_BYTES (48*WST2*4)      // 52224

__device__ float g_gi0[(size_t)Mm*Ss*Bb*Gg];
__device__ float g_y0m[(size_t)Mm*Pp*Ss*Bb*Hh];
__device__ float g_gi1[(size_t)Mm*Pp*Ss*Bb*Gg];
__device__ float g_a1 [(size_t)Mm*Pp*Ss*Bb*Hh];
__device__ float g_h0a[Mm*Rr*Hh];
__device__ float g_h0b[Mm*Rr*Hh];
__device__ float g_h1a[Mm*Rr*Hh];
__device__ float g_h1b[Mm*Rr*Hh];
// packed SINGLE-fp16 h, permw fragment layout, double buffered: 64 uint4 (256 words) per row
__device__ uint4 g_hp0a[Mm*Rr*64];
__device__ uint4 g_hp0b[Mm*Rr*64];
__device__ uint4 g_hp1a[Mm*Rr*64];
__device__ uint4 g_hp1b[Mm*Rr*64];
// single-fp16 recurrent weights: [layer][Mm][3H] rows x 256 fp16x2 words
__device__ uint4 g_whf4[2 * Mm * Gg * 64];
__device__ unsigned g_sync[8];

__device__ __forceinline__ float tf32r(float x) {
    uint32_t u;
    asm("cvt.rna.tf32.f32 %0, %1;" : "=r"(u) : "f"(x));
    return __uint_as_float(u);
}

__device__ __forceinline__ void mma_tf32(float c[4], const uint32_t a[4], const uint32_t b[2]) {
    asm volatile(
        "mma.sync.aligned.m16n8k8.row.col.f32.tf32.tf32.f32 "
        "{%0,%1,%2,%3},{%4,%5,%6,%7},{%8,%9},{%0,%1,%2,%3};"
        : "+f"(c[0]), "+f"(c[1]), "+f"(c[2]), "+f"(c[3])
        : "r"(a[0]), "r"(a[1]), "r"(a[2]), "r"(a[3]), "r"(b[0]), "r"(b[1]));
}

__device__ __forceinline__ void mma_f16(float c[4], const uint32_t a[4], const uint32_t b[2]) {
    asm volatile(
        "mma.sync.aligned.m16n8k16.row.col.f32.f16.f16.f32 "
        "{%0,%1,%2,%3},{%4,%5,%6,%7},{%8,%9},{%0,%1,%2,%3};"
        : "+f"(c[0]), "+f"(c[1]), "+f"(c[2]), "+f"(c[3])
        : "r"(a[0]), "r"(a[1]), "r"(a[2]), "r"(a[3]), "r"(b[0]), "r"(b[1]));
}

__device__ __forceinline__ float sigmoidf_(float x) { return 1.0f / (1.0f + expf(-x)); }

// W/h smem+gmem permutation: supergroup of 16 words = 2 k16-iters; for thread tg the
// uint4 at sg*16+tg*4 holds [i0 w_tg, i0 w_(tg+4), i1 w_tg, i1 w_(tg+4)].
__device__ __forceinline__ int permw(int kp) {
    int sg = kp >> 4;
    int rr = kp & 7;
    int grp = (kp >> 3) & 1;
    return sg * 16 + (rr & 3) * 4 + grp * 2 + (rr >> 2);
}

__global__ void init_hidden_kernel(const float* __restrict__ hidden,
                                   float* __restrict__ h0, float* __restrict__ h1,
                                   unsigned* __restrict__ p0, unsigned* __restrict__ p1,
                                   unsigned* __restrict__ sync)
{
    int idx = blockIdx.x * blockDim.x + threadIdx.x;
    if (blockIdx.x == 0 && threadIdx.x < 8) sync[threadIdx.x] = 0u;
    const int n2 = Mm*Pp*Bb*256;
    if (idx >= n2) return;
    int mp  = idx / (Bb*256);
    int rem = idx % (Bb*256);
    int b  = rem >> 8;
    int kp = rem & 255;
    float2 v0 = *reinterpret_cast<const float2*>(&hidden[((size_t)mp*Ll + 0)*Bb*Hh + b*Hh + 2*kp]);
    float2 v1 = *reinterpret_cast<const float2*>(&hidden[((size_t)mp*Ll + 1)*Bb*Hh + b*Hh + 2*kp]);
    *reinterpret_cast<float2*>(&h0[((size_t)mp*Bb + b)*Hh + 2*kp]) = v0;
    *reinterpret_cast<float2*>(&h1[((size_t)mp*Bb + b)*Hh + 2*kp]) = v1;
    __half2 q0 = __floats2half2_rn(v0.x, v0.y);
    __half2 q1 = __floats2half2_rn(v1.x, v1.y);
    p0[((size_t)mp*Bb + b)*256 + permw(kp)] = *reinterpret_cast<unsigned*>(&q0);
    p1[((size_t)mp*Bb + b)*256 + permw(kp)] = *reinterpret_cast<unsigned*>(&q1);
}

__global__ void hidden_out_kernel(const float* __restrict__ h0, const float* __restrict__ h1,
                                  float* __restrict__ out)
{
    int idx = blockIdx.x * blockDim.x + threadIdx.x;
    const int n = Mm*Pp*Bb*Hh;
    if (idx >= n) return;
    int mp  = idx / (Bb*Hh);
    int rem = idx % (Bb*Hh);
    out[((size_t)mp*Ll + 0)*Bb*Hh + rem] = h0[idx];
    out[((size_t)mp*Ll + 1)*Bb*Hh + rem] = h1[idx];
}

__global__ void split_w16_kernel(const float* __restrict__ w0, const float* __restrict__ w1,
                                 unsigned* __restrict__ outp)
{
    const int n = Mm * Gg * 256;
    int idx = blockIdx.x * blockDim.x + threadIdx.x;
    if (idx >= 2 * n) return;
    const float* src = (idx < n) ? w0 : w1;
    int wi = (idx < n) ? idx : idx - n;
    float2 x = *reinterpret_cast<const float2*>(src + (size_t)wi * 2);
    __half2 h = __floats2half2_rn(x.x, x.y);
    outp[idx] = *reinterpret_cast<unsigned*>(&h);
}

__global__ __launch_bounds__(256) void gemm_tf32_bias(
    const float* __restrict__ A, long aStride,
    const float* __restrict__ W, long wStride,
    const float* __restrict__ bias, int bStride,
    float* __restrict__ C, long cStride,
    int rows, int N, int K)
{
    const int batch = blockIdx.z;
    A    += (long)batch * aStride;
    W    += (long)batch * wStride;
    bias += (long)batch * bStride;
    C    += (long)batch * cStride;

    const int r0 = blockIdx.y * 128;
    const int n0 = blockIdx.x * 64;

    __shared__ float As[128][36];
    __shared__ float Bs[64][36];

    const int tid  = threadIdx.x;
    const int lane = tid & 31;
    const int w    = tid >> 5;
    const int wr   = w >> 1;
    const int wc   = w & 1;
    const int gID  = lane >> 2;
    const int tig  = lane & 3;

    float c[2][4][4];
#pragma unroll
    for (int mi = 0; mi < 2; mi++)
#pragma unroll
        for (int ni = 0; ni < 4; ni++)
#pragma unroll
            for (int q = 0; q < 4; q++) c[mi][ni][q] = 0.f;

    for (int k0 = 0; k0 < K; k0 += 32) {
#pragma unroll
        for (int l = 0; l < 4; l++) {
            int f = tid + l * 256;
            int row = f >> 3;
            int kg  = f & 7;
            float4 v = *reinterpret_cast<const float4*>(&A[(long)(r0 + row) * K + k0 + kg * 4]);
            float4 t;
            t.x = tf32r(v.x); t.y = tf32r(v.y); t.z = tf32r(v.z); t.w = tf32r(v.w);
            *reinterpret_cast<float4*>(&As[row][kg * 4]) = t;
        }
#pragma unroll
        for (int l = 0; l < 2; l++) {
            int f = tid + l * 256;
            int col = f >> 3;
            int kg  = f & 7;
            float4 v = *reinterpret_cast<const float4*>(&W[(long)(n0 + col) * K + k0 + kg * 4]);
            float4 t;
            t.x = tf32r(v.x); t.y = tf32r(v.y); t.z = tf32r(v.z); t.w = tf32r(v.w);
            *reinterpret_cast<float4*>(&Bs[col][kg * 4]) = t;
        }
        __syncthreads();

#pragma unroll
        for (int k8 = 0; k8 < 4; k8++) {
            const int kb = k8 * 8;
            uint32_t af[2][4];
#pragma unroll
            for (int mi = 0; mi < 2; mi++) {
                int rb = wr * 32 + mi * 16 + gID;
                af[mi][0] = __float_as_uint(As[rb    ][kb + tig]);
                af[mi][1] = __float_as_uint(As[rb + 8][kb + tig]);
                af[mi][2] = __float_as_uint(As[rb    ][kb + 4 + tig]);
                af[mi][3] = __float_as_uint(As[rb + 8][kb + 4 + tig]);
            }
            uint32_t bf[4][2];
#pragma unroll
            for (int ni = 0; ni < 4; ni++) {
                int cb = wc * 32 + ni * 8 + gID;
                bf[ni][0] = __float_as_uint(Bs[cb][kb + tig]);
                bf[ni][1] = __float_as_uint(Bs[cb][kb + 4 + tig]);
            }
#pragma unroll
            for (int mi = 0; mi < 2; mi++)
#pragma unroll
                for (int ni = 0; ni < 4; ni++)
                    mma_tf32(c[mi][ni], af[mi], bf[ni]);
        }
        __syncthreads();
    }

#pragma unroll
    for (int mi = 0; mi < 2; mi++) {
#pragma unroll
        for (int ni = 0; ni < 4; ni++) {
            int row = r0 + wr * 32 + mi * 16 + gID;
            int col = n0 + wc * 32 + ni * 8 + 2 * tig;
            float b0 = bias[col], b1 = bias[col + 1];
            float2 v0 = make_float2(c[mi][ni][0] + b0, c[mi][ni][1] + b1);
            float2 v1 = make_float2(c[mi][ni][2] + b0, c[mi][ni][3] + b1);
            *reinterpret_cast<float2*>(&C[(long)row * N + col]) = v0;
            *reinterpret_cast<float2*>(&C[(long)(row + 8) * N + col]) = v1;
        }
    }
}

// ================= persistent GRU scan: single-fp16 1-term mma =================
// grid = 128 blocks (m = bx>>5, j0 = (bx&31)*16), 256 threads = 8 warps.
// warp w = rowgroup (16 rows), full K=512, 48 gate-cols of this j-slice.
template<int LAYER>
__global__ __launch_bounds__(256, 1) void gru_scan(
    float* __restrict__ bufA, float* __restrict__ bufB,
    unsigned* __restrict__ pakA, unsigned* __restrict__ pakB,
    const float* __restrict__ gi,
    const uint4* __restrict__ whf4,
    const float* __restrict__ bhh,
    const float* __restrict__ dm,
    float* __restrict__ outact,
    unsigned* __restrict__ syncctr)
{
    extern __shared__ unsigned Wpk[];

    const int bx = blockIdx.x;
    const int m  = bx >> 5;
    const int j0 = (bx & 31) * 16;

    const int tid  = threadIdx.x;
    const int lane = tid & 31;
    const int w    = tid >> 5;
    const int g    = lane >> 2;
    const int tg   = lane & 3;

    // load single-fp16 weights into smem, permw layout
    {
        const uint4* wb = whf4 + (long)m * Gg * 64;
        for (int f = tid; f < 48 * 64; f += 256) {
            int cc = f >> 6, q = f & 63;
            int gr = (cc >> 4) * Hh + j0 + (cc & 15);
            uint4 v = wb[(long)gr * 64 + q];
            unsigned wv[4] = {v.x, v.y, v.z, v.w};
#pragma unroll
            for (int e = 0; e < 4; e++)
                Wpk[cc * WST2 + permw(q * 4 + e)] = wv[e];
        }
    }
    __syncthreads();

    const long hb  = (long)m * Rr * Hh;
    const long hb4 = (long)m * Rr * 64;   // uint4 units
    const int  ar0 = w * 16 + g;
    const int  ar1 = w * 16 + 8 + g;

    float b_r[2][2], b_z[2][2], b_n[2][2];
#pragma unroll
    for (int u = 0; u < 2; u++)
#pragma unroll
        for (int jj = 0; jj < 2; jj++) {
            int j = j0 + u * 8 + 2 * tg + jj;
            b_r[u][jj] = __ldg(&bhh[m * Gg + j]);
            b_z[u][jj] = __ldg(&bhh[m * Gg + Hh + j]);
            b_n[u][jj] = __ldg(&bhh[m * Gg + 2 * Hh + j]);
        }

    float2 gr2[2][2], gz2[2][2], gn2[2][2], dm2[2][2];
    auto prefetch_gi = [&](int t) {
#pragma unroll
        for (int rh = 0; rh < 2; rh++) {
            int row = w * 16 + rh * 8 + g;
            int p = row >> 5, b = row & 31;
            long girow = (LAYER == 0)
                ? ((long)(m * Ss + t) * Bb + b) * Gg
                : ((long)((m * Pp + p) * Ss + t) * Bb + b) * Gg;
            long obase = (((long)(m * Pp + p) * Ss + t) * Bb + b) * Hh;
#pragma unroll
            for (int u = 0; u < 2; u++) {
                int j = j0 + u * 8 + 2 * tg;
                gr2[rh][u] = __ldcg(reinterpret_cast<const float2*>(&gi[girow + j]));
                gz2[rh][u] = __ldcg(reinterpret_cast<const float2*>(&gi[girow + Hh + j]));
                gn2[rh][u] = __ldcg(reinterpret_cast<const float2*>(&gi[girow + 2 * Hh + j]));
                if (LAYER == 0)
                    dm2[rh][u] = __ldcg(reinterpret_cast<const float2*>(&dm[obase + j]));
            }
        }
    };
    prefetch_gi(0);

    // packed-h store position (u=0,1 words adjacent under permw)
    const int s_   = bx & 31;
    const int pkpos = (s_ >> 1) * 16 + tg * 4 + (s_ & 1) * 2;   // word offset within row

    for (int t = 0; t < Ss; t++) {
        const float* hc = (t & 1) ? bufB : bufA;
        float*       hn = (t & 1) ? bufA : bufB;
        const uint4* pc = reinterpret_cast<const uint4*>((t & 1) ? pakB : pakA);
        unsigned*    pn = (t & 1) ? pakA : pakB;

        float2 ho2[2][2];
#pragma unroll
        for (int rh = 0; rh < 2; rh++) {
            int row = w * 16 + rh * 8 + g;
#pragma unroll
            for (int u = 0; u < 2; u++) {
                int j = j0 + u * 8 + 2 * tg;
                ho2[rh][u] = __ldcg(reinterpret_cast<const float2*>(&hc[hb + (long)row * Hh + j]));
            }
        }

        float cA[6][4];
#pragma unroll
        for (int e = 0; e < 24; e++) (&cA[0][0])[e] = 0.f;

        auto fetchA = [&](int p, uint4* P) {
            P[0] = __ldcg(pc + hb4 + (long)ar0 * 64 + p * 4 + tg);
            P[1] = __ldcg(pc + hb4 + (long)ar1 * 64 + p * 4 + tg);
        };
        auto loadBpair = [&](int p, uint4* Bq) {
#pragma unroll
            for (int tI = 0; tI < 6; tI++)
                Bq[tI] = *reinterpret_cast<const uint4*>(Wpk + (tI * 8 + g) * WST2 + p * 16 + tg * 4);
        };
        // one iter-pair: 12 mma (6 per k16 iter), A from uint4 pair
        auto mmaPair = [&](const uint4* P, const uint4* Bq) {
            uint32_t a0[4] = {P[0].x, P[1].x, P[0].y, P[1].y};
            uint32_t a1[4] = {P[0].z, P[1].z, P[0].w, P[1].w};
#pragma unroll
            for (int tI = 0; tI < 6; tI++) {
                uint32_t b0[2] = {Bq[tI].x, Bq[tI].y};
                mma_f16(cA[tI], a0, b0);
            }
#pragma unroll
            for (int tI = 0; tI < 6; tI++) {
                uint32_t b1[2] = {Bq[tI].z, Bq[tI].w};
                mma_f16(cA[tI], a1, b1);
            }
        };

        uint4 P[2][2];
        uint4 Bq[2][6];
        fetchA(0, P[0]);
        loadBpair(0, Bq[0]);
#pragma unroll
        for (int p = 0; p < 16; p++) {
            if (p < 15) {
                fetchA(p + 1, P[(p + 1) & 1]);
                loadBpair(p + 1, Bq[(p + 1) & 1]);
            }
            mmaPair(P[p & 1], Bq[p & 1]);
        }

        // ---- epilogue: gates + h update ----
#pragma unroll
        for (int rh = 0; rh < 2; rh++) {
            int row = w * 16 + rh * 8 + g;
            int p = row >> 5, b = row & 31;
            long obase = (((long)(m * Pp + p) * Ss + t) * Bb + b) * Hh;
            unsigned pk[2];
#pragma unroll
            for (int u = 0; u < 2; u++) {
                int j = j0 + u * 8 + 2 * tg;
                float hv[2];
#pragma unroll
                for (int jj = 0; jj < 2; jj++) {
                    int qi = rh * 2 + jj;
                    float ghr = cA[0 + u][qi] + b_r[u][jj];
                    float ghz = cA[2 + u][qi] + b_z[u][jj];
                    float ghn = cA[4 + u][qi] + b_n[u][jj];
                    float gih = (jj == 0) ? gr2[rh][u].x : gr2[rh][u].y;
                    float giz = (jj == 0) ? gz2[rh][u].x : gz2[rh][u].y;
                    float gin = (jj == 0) ? gn2[rh][u].x : gn2[rh][u].y;
                    float hold = (jj == 0) ? ho2[rh][u].x : ho2[rh][u].y;
                    float rg = sigmoidf_(gih + ghr);
                    float zg = sigmoidf_(giz + ghz);
                    float ng = tanhf(gin + rg * ghn);
                    hv[jj] = (1.0f - zg) * ng + zg * hold;
                }
                __stcg(reinterpret_cast<float2*>(&hn[hb + (long)row * Hh + j]),
                       make_float2(hv[0], hv[1]));
                __half2 q = __floats2half2_rn(hv[0], hv[1]);
                pk[u] = *reinterpret_cast<unsigned*>(&q);
                float2 oa;
                if (LAYER == 0) {
                    oa = make_float2(hv[0] * dm2[rh][u].x, hv[1] * dm2[rh][u].y);
                } else {
                    oa = make_float2(fmaxf(hv[0], 0.f) + 0.01f * fminf(hv[0], 0.f),
                                     fmaxf(hv[1], 0.f) + 0.01f * fminf(hv[1], 0.f));
                }
                __stcg(reinterpret_cast<float2*>(&outact[obase + j]), oa);
            }
            __stcg(reinterpret_cast<uint2*>(pn + ((long)m * Rr + row) * 256 + pkpos),
                   make_uint2(pk[0], pk[1]));
        }

        if (t + 1 < Ss) prefetch_gi(t + 1);

        // ---- per-model grid barrier ----
        __syncthreads();
        if (tid == 0) {
            __threadfence();
            atomicAdd(&syncctr[m], 1u);
            unsigned target = 32u * (unsigned)(t + 1);
            volatile unsigned* vc = (volatile unsigned*)&syncctr[m];
            while (*vc < target) __nanosleep(32);
        }
        __syncthreads();
    }
}

__global__ void meanvar_kernel(const float* __restrict__ preds,
                               float* __restrict__ out_mean, float* __restrict__ out_var)
{
    const int n = Ss * Bb * Oo;
    int idx = blockIdx.x * blockDim.x + threadIdx.x;
    if (idx >= n) return;
    float v[16];
    float s = 0.f;
#pragma unroll
    for (int mp = 0; mp < 16; mp++) {
        v[mp] = preds[(long)mp * n + idx];
        s += v[mp];
    }
    float mu = s * (1.0f / 16.0f);
    float qq = 0.f;
#pragma unroll
    for (int mp = 0; mp < 16; mp++) {
        float d = v[mp] - mu;
        qq += d * d;
    }
    out_mean[idx] = mu;
    out_var[idx]  = qq * (1.0f / 15.0f);
}

extern "C" void kernel_launch(void* const* d_in, const int* in_sizes, int n_in,
                              void* d_out, int out_size)
{
    const float* input  = (const float*)d_in[0];
    const float* hidden = (const float*)d_in[1];
    const float* w_ih0  = (const float*)d_in[2];
    const float* w_hh0  = (const float*)d_in[3];
    const float* b_ih0  = (const float*)d_in[4];
    const float* b_hh0  = (const float*)d_in[5];
    const float* w_ih1  = (const float*)d_in[6];
    const float* w_hh1  = (const float*)d_in[7];
    const float* b_ih1  = (const float*)d_in[8];
    const float* b_hh1  = (const float*)d_in[9];
    const float* lin_w  = (const float*)d_in[10];
    const float* lin_b  = (const float*)d_in[11];
    const float* dm     = (const float*)d_in[12];

    float* out = (float*)d_out;
    float* out_mean   = out;
    float* out_var    = out + (size_t)Ss * Bb * Oo;
    float* preds      = out + 2 * (size_t)Ss * Bb * Oo;
    float* hidden_out = preds + (size_t)Mm * Pp * Ss * Bb * Oo;

    float *gi0, *y0m, *gi1, *a1, *h0a, *h0b, *h1a, *h1b;
    uint4 *p0a, *p0b, *p1a, *p1b, *whf4;
    unsigned* syncp;
    cudaGetSymbolAddress((void**)&gi0, g_gi0);
    cudaGetSymbolAddress((void**)&y0m, g_y0m);
    cudaGetSymbolAddress((void**)&gi1, g_gi1);
    cudaGetSymbolAddress((void**)&a1,  g_a1);
    cudaGetSymbolAddress((void**)&h0a, g_h0a);
    cudaGetSymbolAddress((void**)&h0b, g_h0b);
    cudaGetSymbolAddress((void**)&h1a, g_h1a);
    cudaGetSymbolAddress((void**)&h1b, g_h1b);
    cudaGetSymbolAddress((void**)&p0a, g_hp0a);
    cudaGetSymbolAddress((void**)&p0b, g_hp0b);
    cudaGetSymbolAddress((void**)&p1a, g_hp1a);
    cudaGetSymbolAddress((void**)&p1b, g_hp1b);
    cudaGetSymbolAddress((void**)&whf4, g_whf4);
    cudaGetSymbolAddress((void**)&syncp, g_sync);

    cudaFuncSetAttribute(gru_scan<0>, cudaFuncAttributeMaxDynamicSharedMemorySize, SCAN_SMEM_BYTES);
    cudaFuncSetAttribute(gru_scan<1>, cudaFuncAttributeMaxDynamicSharedMemorySize, SCAN_SMEM_BYTES);

    {
        int n2 = 2 * Mm * Gg * 256;
        split_w16_kernel<<<(n2 + 255) / 256, 256>>>(w_hh0, w_hh1, (unsigned*)whf4);
    }
    {
        int n2 = Mm * Pp * Bb * 256;
        init_hidden_kernel<<<(n2 + 255) / 256, 256>>>(hidden, h0a, h1a,
                                                      (unsigned*)p0a, (unsigned*)p1a, syncp);
    }
    {
        dim3 grid(Gg / 64, (Ss * Bb) / 128, Mm);
        gemm_tf32_bias<<<grid, 256>>>(input, 0L,
                                      w_ih0, (long)Gg * Ii,
                                      b_ih0, Gg,
                                      gi0, (long)Ss * Bb * Gg,
                                      Ss * Bb, Gg, Ii);
    }

    gru_scan<0><<<128, 256, SCAN_SMEM_BYTES>>>(h0a, h0b, (unsigned*)p0a, (unsigned*)p0b, gi0,
                                               whf4, b_hh0, dm, y0m, syncp);

    {
        dim3 grid(Gg / 64, (Pp * Ss * Bb) / 128, Mm);
        gemm_tf32_bias<<<grid, 256>>>(y0m, (long)Pp * Ss * Bb * Hh,
                                      w_ih1, (long)Gg * Hh,
                                      b_ih1, Gg,
                                      gi1, (long)Pp * Ss * Bb * Gg,
                                      Pp * Ss * Bb, Gg, Hh);
    }

    gru_scan<1><<<128, 256, SCAN_SMEM_BYTES>>>(h1a, h1b, (unsigned*)p1a, (unsigned*)p1b, gi1,
                                               whf4 + (long)Mm * Gg * 64, b_hh1,
                                               nullptr, a1, syncp + 4);

    {
        dim3 grid(Oo / 64, (Pp * Ss * Bb) / 128, Mm);
        gemm_tf32_bias<<<grid, 256>>>(a1, (long)Pp * Ss * Bb * Hh,
                                      lin_w, (long)Oo * Hh,
                                      lin_b, Oo,
                                      preds, (long)Pp * Ss * Bb * Oo,
                                      Pp * Ss * Bb, Oo, Hh);
    }

    meanvar_kernel<<<(Ss * Bb * Oo + 255) / 256, 256>>>(preds, out_mean, out_var);
    hidden_out_kernel<<<(Mm*Pp*Bb*Hh + 255) / 256, 256>>>(h0a, h1a, hidden_out);
}

// round 15
// speedup vs baseline: 1.5065x; 1.0444x over previous
#include <cuda_runtime.h>
#include <cuda_bf16.h>
#include <cuda_fp16.h>
#include <math.h>
#include <stdint.h>

#define Mm 4
#define Pp 4
#define Ll 2
#define Ss 256
#define Bb 32
#define Ii 256
#define Hh 512
#define Oo 256
#define Gg (3*Hh)
#define Rr (Pp*Bb)

#define WST2 272                         // smem words per gate-col row (256 + 16 pad)
#define SCAN_SMEM_BYTES (48*WST2*4)      // 52224

__device__ float g_gi0[(size_t)Mm*Ss*Bb*Gg];
__device__ float g_y0m[(size_t)Mm*Pp*Ss*Bb*Hh];
__device__ float g_gi1[(size_t)Mm*Pp*Ss*Bb*Gg];
__device__ float g_a1 [(size_t)Mm*Pp*Ss*Bb*Hh];
__device__ float g_h0a[Mm*Rr*Hh];
__device__ float g_h0b[Mm*Rr*Hh];
__device__ float g_h1a[Mm*Rr*Hh];
__device__ float g_h1b[Mm*Rr*Hh];
// packed SINGLE-fp16 h, permw fragment layout, double buffered: 64 uint4 (256 words) per row
__device__ uint4 g_hp0a[Mm*Rr*64];
__device__ uint4 g_hp0b[Mm*Rr*64];
__device__ uint4 g_hp1a[Mm*Rr*64];
__device__ uint4 g_hp1b[Mm*Rr*64];
// single-fp16 recurrent weights: [layer][Mm][3H] rows x 256 fp16x2 words
__device__ uint4 g_whf4[2 * Mm * Gg * 64];
__device__ unsigned g_sync[8];

__device__ __forceinline__ void mma_f16(float c[4], const uint32_t a[4], const uint32_t b[2]) {
    asm volatile(
        "mma.sync.aligned.m16n8k16.row.col.f32.f16.f16.f32 "
        "{%0,%1,%2,%3},{%4,%5,%6,%7},{%8,%9},{%0,%1,%2,%3};"
        : "+f"(c[0]), "+f"(c[1]), "+f"(c[2]), "+f"(c[3])
        : "r"(a[0]), "r"(a[1]), "r"(a[2]), "r"(a[3]), "r"(b[0]), "r"(b[1]));
}

__device__ __forceinline__ float sigmoidf_(float x) { return 1.0f / (1.0f + expf(-x)); }

__device__ __forceinline__ unsigned pack_h2(float x0, float x1) {
    __half2 h = __floats2half2_rn(x0, x1);
    return *reinterpret_cast<unsigned*>(&h);
}

// W/h smem+gmem permutation: supergroup of 16 words = 2 k16-iters; for thread tg the
// uint4 at sg*16+tg*4 holds [i0 w_tg, i0 w_(tg+4), i1 w_tg, i1 w_(tg+4)].
__device__ __forceinline__ int permw(int kp) {
    int sg = kp >> 4;
    int rr = kp & 7;
    int grp = (kp >> 3) & 1;
    return sg * 16 + (rr & 3) * 4 + grp * 2 + (rr >> 2);
}

__global__ void init_hidden_kernel(const float* __restrict__ hidden,
                                   float* __restrict__ h0, float* __restrict__ h1,
                                   unsigned* __restrict__ p0, unsigned* __restrict__ p1,
                                   unsigned* __restrict__ sync)
{
    int idx = blockIdx.x * blockDim.x + threadIdx.x;
    if (blockIdx.x == 0 && threadIdx.x < 8) sync[threadIdx.x] = 0u;
    const int n2 = Mm*Pp*Bb*256;
    if (idx >= n2) return;
    int mp  = idx / (Bb*256);
    int rem = idx % (Bb*256);
    int b  = rem >> 8;
    int kp = rem & 255;
    float2 v0 = *reinterpret_cast<const float2*>(&hidden[((size_t)mp*Ll + 0)*Bb*Hh + b*Hh + 2*kp]);
    float2 v1 = *reinterpret_cast<const float2*>(&hidden[((size_t)mp*Ll + 1)*Bb*Hh + b*Hh + 2*kp]);
    *reinterpret_cast<float2*>(&h0[((size_t)mp*Bb + b)*Hh + 2*kp]) = v0;
    *reinterpret_cast<float2*>(&h1[((size_t)mp*Bb + b)*Hh + 2*kp]) = v1;
    p0[((size_t)mp*Bb + b)*256 + permw(kp)] = pack_h2(v0.x, v0.y);
    p1[((size_t)mp*Bb + b)*256 + permw(kp)] = pack_h2(v1.x, v1.y);
}

__global__ void hidden_out_kernel(const float* __restrict__ h0, const float* __restrict__ h1,
                                  float* __restrict__ out)
{
    int idx = blockIdx.x * blockDim.x + threadIdx.x;
    const int n = Mm*Pp*Bb*Hh;
    if (idx >= n) return;
    int mp  = idx / (Bb*Hh);
    int rem = idx % (Bb*Hh);
    out[((size_t)mp*Ll + 0)*Bb*Hh + rem] = h0[idx];
    out[((size_t)mp*Ll + 1)*Bb*Hh + rem] = h1[idx];
}

__global__ void split_w16_kernel(const float* __restrict__ w0, const float* __restrict__ w1,
                                 unsigned* __restrict__ outp)
{
    const int n = Mm * Gg * 256;
    int idx = blockIdx.x * blockDim.x + threadIdx.x;
    if (idx >= 2 * n) return;
    const float* src = (idx < n) ? w0 : w1;
    int wi = (idx < n) ? idx : idx - n;
    float2 x = *reinterpret_cast<const float2*>(src + (size_t)wi * 2);
    outp[idx] = pack_h2(x.x, x.y);
}

// ================= FP16 tensor-core GEMM with bias (feedforward) =================
// Same tiling as before (BM=128, BN=64, BK=32, 8 warps 4x2, warp tile 32x32),
// but fp16 operands via m16n8k16 (half the mma count, half the smem/LDS).
__global__ __launch_bounds__(256) void gemm_f16_bias(
    const float* __restrict__ A, long aStride,
    const float* __restrict__ W, long wStride,
    const float* __restrict__ bias, int bStride,
    float* __restrict__ C, long cStride,
    int rows, int N, int K)
{
    const int batch = blockIdx.z;
    A    += (long)batch * aStride;
    W    += (long)batch * wStride;
    bias += (long)batch * bStride;
    C    += (long)batch * cStride;

    const int r0 = blockIdx.y * 128;
    const int n0 = blockIdx.x * 64;

    __shared__ unsigned As[128][18];   // 32 halves (16 words) + 2 pad
    __shared__ unsigned Bs[64][18];

    const int tid  = threadIdx.x;
    const int lane = tid & 31;
    const int w    = tid >> 5;
    const int wr   = w >> 1;
    const int wc   = w & 1;
    const int gID  = lane >> 2;
    const int tig  = lane & 3;

    float c[2][4][4];
#pragma unroll
    for (int mi = 0; mi < 2; mi++)
#pragma unroll
        for (int ni = 0; ni < 4; ni++)
#pragma unroll
            for (int q = 0; q < 4; q++) c[mi][ni][q] = 0.f;

    for (int k0 = 0; k0 < K; k0 += 32) {
        // A tile 128x32 floats -> fp16 pairs: 4 float4/thread
#pragma unroll
        for (int l = 0; l < 4; l++) {
            int f = tid + l * 256;
            int row = f >> 3;
            int kg  = f & 7;
            float4 v = *reinterpret_cast<const float4*>(&A[(long)(r0 + row) * K + k0 + kg * 4]);
            As[row][kg * 2]     = pack_h2(v.x, v.y);
            As[row][kg * 2 + 1] = pack_h2(v.z, v.w);
        }
        // B tile 64x32 floats: 2 float4/thread
#pragma unroll
        for (int l = 0; l < 2; l++) {
            int f = tid + l * 256;
            int col = f >> 3;
            int kg  = f & 7;
            float4 v = *reinterpret_cast<const float4*>(&W[(long)(n0 + col) * K + k0 + kg * 4]);
            Bs[col][kg * 2]     = pack_h2(v.x, v.y);
            Bs[col][kg * 2 + 1] = pack_h2(v.z, v.w);
        }
        __syncthreads();

#pragma unroll
        for (int gk = 0; gk < 2; gk++) {
            const int kb = gk * 8;   // word offset of this k16 group
            uint32_t af[2][4];
#pragma unroll
            for (int mi = 0; mi < 2; mi++) {
                int rb = wr * 32 + mi * 16 + gID;
                af[mi][0] = As[rb    ][kb + tig];
                af[mi][1] = As[rb + 8][kb + tig];
                af[mi][2] = As[rb    ][kb + 4 + tig];
                af[mi][3] = As[rb + 8][kb + 4 + tig];
            }
            uint32_t bf[4][2];
#pragma unroll
            for (int ni = 0; ni < 4; ni++) {
                int cb = wc * 32 + ni * 8 + gID;
                bf[ni][0] = Bs[cb][kb + tig];
                bf[ni][1] = Bs[cb][kb + 4 + tig];
            }
#pragma unroll
            for (int mi = 0; mi < 2; mi++)
#pragma unroll
                for (int ni = 0; ni < 4; ni++)
                    mma_f16(c[mi][ni], af[mi], bf[ni]);
        }
        __syncthreads();
    }

#pragma unroll
    for (int mi = 0; mi < 2; mi++) {
#pragma unroll
        for (int ni = 0; ni < 4; ni++) {
            int row = r0 + wr * 32 + mi * 16 + gID;
            int col = n0 + wc * 32 + ni * 8 + 2 * tig;
            float b0 = bias[col], b1 = bias[col + 1];
            float2 v0 = make_float2(c[mi][ni][0] + b0, c[mi][ni][1] + b1);
            float2 v1 = make_float2(c[mi][ni][2] + b0, c[mi][ni][3] + b1);
            *reinterpret_cast<float2*>(&C[(long)row * N + col]) = v0;
            *reinterpret_cast<float2*>(&C[(long)(row + 8) * N + col]) = v1;
        }
    }
}

// ================= persistent GRU scan: single-fp16 1-term mma (unchanged from R14) =================
template<int LAYER>
__global__ __launch_bounds__(256, 1) void gru_scan(
    float* __restrict__ bufA, float* __restrict__ bufB,
    unsigned* __restrict__ pakA, unsigned* __restrict__ pakB,
    const float* __restrict__ gi,
    const uint4* __restrict__ whf4,
    const float* __restrict__ bhh,
    const float* __restrict__ dm,
    float* __restrict__ outact,
    unsigned* __restrict__ syncctr)
{
    extern __shared__ unsigned Wpk[];

    const int bx = blockIdx.x;
    const int m  = bx >> 5;
    const int j0 = (bx & 31) * 16;

    const int tid  = threadIdx.x;
    const int lane = tid & 31;
    const int w    = tid >> 5;
    const int g    = lane >> 2;
    const int tg   = lane & 3;

    {
        const uint4* wb = whf4 + (long)m * Gg * 64;
        for (int f = tid; f < 48 * 64; f += 256) {
            int cc = f >> 6, q = f & 63;
            int gr = (cc >> 4) * Hh + j0 + (cc & 15);
            uint4 v = wb[(long)gr * 64 + q];
            unsigned wv[4] = {v.x, v.y, v.z, v.w};
#pragma unroll
            for (int e = 0; e < 4; e++)
                Wpk[cc * WST2 + permw(q * 4 + e)] = wv[e];
        }
    }
    __syncthreads();

    const long hb  = (long)m * Rr * Hh;
    const long hb4 = (long)m * Rr * 64;
    const int  ar0 = w * 16 + g;
    const int  ar1 = w * 16 + 8 + g;

    float b_r[2][2], b_z[2][2], b_n[2][2];
#pragma unroll
    for (int u = 0; u < 2; u++)
#pragma unroll
        for (int jj = 0; jj < 2; jj++) {
            int j = j0 + u * 8 + 2 * tg + jj;
            b_r[u][jj] = __ldg(&bhh[m * Gg + j]);
            b_z[u][jj] = __ldg(&bhh[m * Gg + Hh + j]);
            b_n[u][jj] = __ldg(&bhh[m * Gg + 2 * Hh + j]);
        }

    float2 gr2[2][2], gz2[2][2], gn2[2][2], dm2[2][2];
    auto prefetch_gi = [&](int t) {
#pragma unroll
        for (int rh = 0; rh < 2; rh++) {
            int row = w * 16 + rh * 8 + g;
            int p = row >> 5, b = row & 31;
            long girow = (LAYER == 0)
                ? ((long)(m * Ss + t) * Bb + b) * Gg
                : ((long)((m * Pp + p) * Ss + t) * Bb + b) * Gg;
            long obase = (((long)(m * Pp + p) * Ss + t) * Bb + b) * Hh;
#pragma unroll
            for (int u = 0; u < 2; u++) {
                int j = j0 + u * 8 + 2 * tg;
                gr2[rh][u] = __ldcg(reinterpret_cast<const float2*>(&gi[girow + j]));
                gz2[rh][u] = __ldcg(reinterpret_cast<const float2*>(&gi[girow + Hh + j]));
                gn2[rh][u] = __ldcg(reinterpret_cast<const float2*>(&gi[girow + 2 * Hh + j]));
                if (LAYER == 0)
                    dm2[rh][u] = __ldcg(reinterpret_cast<const float2*>(&dm[obase + j]));
            }
        }
    };
    prefetch_gi(0);

    const int s_   = bx & 31;
    const int pkpos = (s_ >> 1) * 16 + tg * 4 + (s_ & 1) * 2;

    for (int t = 0; t < Ss; t++) {
        const float* hc = (t & 1) ? bufB : bufA;
        float*       hn = (t & 1) ? bufA : bufB;
        const uint4* pc = reinterpret_cast<const uint4*>((t & 1) ? pakB : pakA);
        unsigned*    pn = (t & 1) ? pakA : pakB;

        float2 ho2[2][2];
#pragma unroll
        for (int rh = 0; rh < 2; rh++) {
            int row = w * 16 + rh * 8 + g;
#pragma unroll
            for (int u = 0; u < 2; u++) {
                int j = j0 + u * 8 + 2 * tg;
                ho2[rh][u] = __ldcg(reinterpret_cast<const float2*>(&hc[hb + (long)row * Hh + j]));
            }
        }

        float cA[6][4];
#pragma unroll
        for (int e = 0; e < 24; e++) (&cA[0][0])[e] = 0.f;

        auto fetchA = [&](int p, uint4* P) {
            P[0] = __ldcg(pc + hb4 + (long)ar0 * 64 + p * 4 + tg);
            P[1] = __ldcg(pc + hb4 + (long)ar1 * 64 + p * 4 + tg);
        };
        auto loadBpair = [&](int p, uint4* Bq) {
#pragma unroll
            for (int tI = 0; tI < 6; tI++)
                Bq[tI] = *reinterpret_cast<const uint4*>(Wpk + (tI * 8 + g) * WST2 + p * 16 + tg * 4);
        };
        auto mmaPair = [&](const uint4* P, const uint4* Bq) {
            uint32_t a0[4] = {P[0].x, P[1].x, P[0].y, P[1].y};
            uint32_t a1[4] = {P[0].z, P[1].z, P[0].w, P[1].w};
#pragma unroll
            for (int tI = 0; tI < 6; tI++) {
                uint32_t b0[2] = {Bq[tI].x, Bq[tI].y};
                mma_f16(cA[tI], a0, b0);
            }
#pragma unroll
            for (int tI = 0; tI < 6; tI++) {
                uint32_t b1[2] = {Bq[tI].z, Bq[tI].w};
                mma_f16(cA[tI], a1, b1);
            }
        };

        uint4 P[2][2];
        uint4 Bq[2][6];
        fetchA(0, P[0]);
        loadBpair(0, Bq[0]);
#pragma unroll
        for (int p = 0; p < 16; p++) {
            if (p < 15) {
                fetchA(p + 1, P[(p + 1) & 1]);
                loadBpair(p + 1, Bq[(p + 1) & 1]);
            }
            mmaPair(P[p & 1], Bq[p & 1]);
        }

        // ---- epilogue: gates + h update ----
#pragma unroll
        for (int rh = 0; rh < 2; rh++) {
            int row = w * 16 + rh * 8 + g;
            int p = row >> 5, b = row & 31;
            long obase = (((long)(m * Pp + p) * Ss + t) * Bb + b) * Hh;
            unsigned pk[2];
#pragma unroll
            for (int u = 0; u < 2; u++) {
                int j = j0 + u * 8 + 2 * tg;
                float hv[2];
#pragma unroll
                for (int jj = 0; jj < 2; jj++) {
                    int qi = rh * 2 + jj;
                    float ghr = cA[0 + u][qi] + b_r[u][jj];
                    float ghz = cA[2 + u][qi] + b_z[u][jj];
                    float ghn = cA[4 + u][qi] + b_n[u][jj];
                    float gih = (jj == 0) ? gr2[rh][u].x : gr2[rh][u].y;
                    float giz = (jj == 0) ? gz2[rh][u].x : gz2[rh][u].y;
                    float gin = (jj == 0) ? gn2[rh][u].x : gn2[rh][u].y;
                    float hold = (jj == 0) ? ho2[rh][u].x : ho2[rh][u].y;
                    float rg = sigmoidf_(gih + ghr);
                    float zg = sigmoidf_(giz + ghz);
                    float ng = tanhf(gin + rg * ghn);
                    hv[jj] = (1.0f - zg) * ng + zg * hold;
                }
                __stcg(reinterpret_cast<float2*>(&hn[hb + (long)row * Hh + j]),
                       make_float2(hv[0], hv[1]));
                pk[u] = pack_h2(hv[0], hv[1]);
                float2 oa;
                if (LAYER == 0) {
                    oa = make_float2(hv[0] * dm2[rh][u].x, hv[1] * dm2[rh][u].y);
                } else {
                    oa = make_float2(fmaxf(hv[0], 0.f) + 0.01f * fminf(hv[0], 0.f),
                                     fmaxf(hv[1], 0.f) + 0.01f * fminf(hv[1], 0.f));
                }
                __stcg(reinterpret_cast<float2*>(&outact[obase + j]), oa);
            }
            __stcg(reinterpret_cast<uint2*>(pn + ((long)m * Rr + row) * 256 + pkpos),
                   make_uint2(pk[0], pk[1]));
        }

        if (t + 1 < Ss) prefetch_gi(t + 1);

        // ---- per-model grid barrier ----
        __syncthreads();
        if (tid == 0) {
            __threadfence();
            atomicAdd(&syncctr[m], 1u);
            unsigned target = 32u * (unsigned)(t + 1);
            volatile unsigned* vc = (volatile unsigned*)&syncctr[m];
            while (*vc < target) __nanosleep(32);
        }
        __syncthreads();
    }
}

__global__ void meanvar_kernel(const float* __restrict__ preds,
                               float* __restrict__ out_mean, float* __restrict__ out_var)
{
    const int n = Ss * Bb * Oo;
    int idx = blockIdx.x * blockDim.x + threadIdx.x;
    if (idx >= n) return;
    float v[16];
    float s = 0.f;
#pragma unroll
    for (int mp = 0; mp < 16; mp++) {
        v[mp] = preds[(long)mp * n + idx];
        s += v[mp];
    }
    float mu = s * (1.0f / 16.0f);
    float qq = 0.f;
#pragma unroll
    for (int mp = 0; mp < 16; mp++) {
        float d = v[mp] - mu;
        qq += d * d;
    }
    out_mean[idx] = mu;
    out_var[idx]  = qq * (1.0f / 15.0f);
}

extern "C" void kernel_launch(void* const* d_in, const int* in_sizes, int n_in,
                              void* d_out, int out_size)
{
    const float* input  = (const float*)d_in[0];
    const float* hidden = (const float*)d_in[1];
    const float* w_ih0  = (const float*)d_in[2];
    const float* w_hh0  = (const float*)d_in[3];
    const float* b_ih0  = (const float*)d_in[4];
    const float* b_hh0  = (const float*)d_in[5];
    const float* w_ih1  = (const float*)d_in[6];
    const float* w_hh1  = (const float*)d_in[7];
    const float* b_ih1  = (const float*)d_in[8];
    const float* b_hh1  = (const float*)d_in[9];
    const float* lin_w  = (const float*)d_in[10];
    const float* lin_b  = (const float*)d_in[11];
    const float* dm     = (const float*)d_in[12];

    float* out = (float*)d_out;
    float* out_mean   = out;
    float* out_var    = out + (size_t)Ss * Bb * Oo;
    float* preds      = out + 2 * (size_t)Ss * Bb * Oo;
    float* hidden_out = preds + (size_t)Mm * Pp * Ss * Bb * Oo;

    float *gi0, *y0m, *gi1, *a1, *h0a, *h0b, *h1a, *h1b;
    uint4 *p0a, *p0b, *p1a, *p1b, *whf4;
    unsigned* syncp;
    cudaGetSymbolAddress((void**)&gi0, g_gi0);
    cudaGetSymbolAddress((void**)&y0m, g_y0m);
    cudaGetSymbolAddress((void**)&gi1, g_gi1);
    cudaGetSymbolAddress((void**)&a1,  g_a1);
    cudaGetSymbolAddress((void**)&h0a, g_h0a);
    cudaGetSymbolAddress((void**)&h0b, g_h0b);
    cudaGetSymbolAddress((void**)&h1a, g_h1a);
    cudaGetSymbolAddress((void**)&h1b, g_h1b);
    cudaGetSymbolAddress((void**)&p0a, g_hp0a);
    cudaGetSymbolAddress((void**)&p0b, g_hp0b);
    cudaGetSymbolAddress((void**)&p1a, g_hp1a);
    cudaGetSymbolAddress((void**)&p1b, g_hp1b);
    cudaGetSymbolAddress((void**)&whf4, g_whf4);
    cudaGetSymbolAddress((void**)&syncp, g_sync);

    cudaFuncSetAttribute(gru_scan<0>, cudaFuncAttributeMaxDynamicSharedMemorySize, SCAN_SMEM_BYTES);
    cudaFuncSetAttribute(gru_scan<1>, cudaFuncAttributeMaxDynamicSharedMemorySize, SCAN_SMEM_BYTES);

    {
        int n2 = 2 * Mm * Gg * 256;
        split_w16_kernel<<<(n2 + 255) / 256, 256>>>(w_hh0, w_hh1, (unsigned*)whf4);
    }
    {
        int n2 = Mm * Pp * Bb * 256;
        init_hidden_kernel<<<(n2 + 255) / 256, 256>>>(hidden, h0a, h1a,
                                                      (unsigned*)p0a, (unsigned*)p1a, syncp);
    }
    {
        dim3 grid(Gg / 64, (Ss * Bb) / 128, Mm);
        gemm_f16_bias<<<grid, 256>>>(input, 0L,
                                     w_ih0, (long)Gg * Ii,
                                     b_ih0, Gg,
                                     gi0, (long)Ss * Bb * Gg,
                                     Ss * Bb, Gg, Ii);
    }

    gru_scan<0><<<128, 256, SCAN_SMEM_BYTES>>>(h0a, h0b, (unsigned*)p0a, (unsigned*)p0b, gi0,
                                               whf4, b_hh0, dm, y0m, syncp);

    {
        dim3 grid(Gg / 64, (Pp * Ss * Bb) / 128, Mm);
        gemm_f16_bias<<<grid, 256>>>(y0m, (long)Pp * Ss * Bb * Hh,
                                     w_ih1, (long)Gg * Hh,
                                     b_ih1, Gg,
                                     gi1, (long)Pp * Ss * Bb * Gg,
                                     Pp * Ss * Bb, Gg, Hh);
    }

    gru_scan<1><<<128, 256, SCAN_SMEM_BYTES>>>(h1a, h1b, (unsigned*)p1a, (unsigned*)p1b, gi1,
                                               whf4 + (long)Mm * Gg * 64, b_hh1,
                                               nullptr, a1, syncp + 4);

    {
        dim3 grid(Oo / 64, (Pp * Ss * Bb) / 128, Mm);
        gemm_f16_bias<<<grid, 256>>>(a1, (long)Pp * Ss * Bb * Hh,
                                     lin_w, (long)Oo * Hh,
                                     lin_b, Oo,
                                     preds, (long)Pp * Ss * Bb * Oo,
                                     Pp * Ss * Bb, Oo, Hh);
    }

    meanvar_kernel<<<(Ss * Bb * Oo + 255) / 256, 256>>>(preds, out_mean, out_var);
    hidden_out_kernel<<<(Mm*Pp*Bb*Hh + 255) / 256, 256>>>(h0a, h1a, hidden_out);
}